// round 14
// baseline (speedup 1.0000x reference)
#include <cuda_runtime.h>
#include <cuda_bf16.h>
#include <cstdint>

#define BATCH 2
#define SEQ   2048
#define DM    1024
#define NH    16
#define DH    64
#define M_TOT (BATCH*SEQ)   // 4096
#define BH_TOT (BATCH*NH)   // 32

// ---------------------------------------------------------------------------
// Scratch (__device__ globals; allocation-free rule)
// ---------------------------------------------------------------------------
__device__ __nv_bfloat16 g_xH[M_TOT*DM],  g_xL[M_TOT*DM];
__device__ __nv_bfloat16 g_WtH[3*DM*DM],  g_WtL[3*DM*DM];      // [n][k], q|k|v
__device__ __nv_bfloat16 g_WoTH[DM*DM],   g_WoTL[DM*DM];       // [n][k]
__device__ __nv_bfloat16 g_QH[BH_TOT*SEQ*DH], g_QL[BH_TOT*SEQ*DH];
__device__ __nv_bfloat16 g_KH[BH_TOT*SEQ*DH], g_KL[BH_TOT*SEQ*DH];
__device__ __nv_bfloat16 g_VtH[BH_TOT*DH*SEQ], g_VtL[BH_TOT*DH*SEQ]; // [bh][d][s]
__device__ __nv_bfloat16 g_attH[M_TOT*DM], g_attL[M_TOT*DM];
__device__ float g_rinv[BH_TOT*SEQ];

// ---------------------------------------------------------------------------
// Helpers
// ---------------------------------------------------------------------------
__device__ __forceinline__ uint32_t smem_u32(const void* p) {
    uint32_t a;
    asm("{ .reg .u64 t; cvta.to.shared.u64 t, %1; cvt.u32.u64 %0, t; }" : "=r"(a) : "l"(p));
    return a;
}
__device__ __forceinline__ void ldsm4(uint32_t* r, uint32_t a) {
    asm volatile("ldmatrix.sync.aligned.m8n8.x4.shared.b16 {%0,%1,%2,%3}, [%4];"
        : "=r"(r[0]), "=r"(r[1]), "=r"(r[2]), "=r"(r[3]) : "r"(a));
}
__device__ __forceinline__ void mma16816(float* d, const uint32_t* a, const uint32_t* b) {
    asm volatile("mma.sync.aligned.m16n8k16.row.col.f32.bf16.bf16.f32 "
        "{%0,%1,%2,%3},{%4,%5,%6,%7},{%8,%9},{%0,%1,%2,%3};"
        : "+f"(d[0]), "+f"(d[1]), "+f"(d[2]), "+f"(d[3])
        : "r"(a[0]), "r"(a[1]), "r"(a[2]), "r"(a[3]), "r"(b[0]), "r"(b[1]));
}
#define CPA16(s, g) asm volatile("cp.async.ca.shared.global [%0], [%1], 16;" :: "r"(s), "l"(g) : "memory")
#define CPA_COMMIT() asm volatile("cp.async.commit_group;" ::: "memory")
#define CPA_WAIT0()  asm volatile("cp.async.wait_group 0;" ::: "memory")
#define CPA_WAIT1()  asm volatile("cp.async.wait_group 1;" ::: "memory")

__device__ __forceinline__ void split2(float v, __nv_bfloat16& h, __nv_bfloat16& l) {
    h = __float2bfloat16(v);
    l = __float2bfloat16(v - __bfloat162float(h));
}
__device__ __forceinline__ uint32_t pack2(__nv_bfloat16 a, __nv_bfloat16 b) {
    __nv_bfloat162 t; t.x = a; t.y = b;
    return *reinterpret_cast<uint32_t*>(&t);
}
__device__ __forceinline__ uint32_t pack2f(float a, float b) {
    __nv_bfloat162 t; t.x = __float2bfloat16(a); t.y = __float2bfloat16(b);
    return *reinterpret_cast<uint32_t*>(&t);
}
__device__ __forceinline__ uint32_t pack2lo(float a, float b) {
    __nv_bfloat16 ha = __float2bfloat16(a), hb = __float2bfloat16(b);
    __nv_bfloat162 t;
    t.x = __float2bfloat16(a - __bfloat162float(ha));
    t.y = __float2bfloat16(b - __bfloat162float(hb));
    return *reinterpret_cast<uint32_t*>(&t);
}

// FMA-pipe exp: exp(x) = 2^(x*log2e); magic-round + degree-5 poly for 2^f.
// rel err <= 2.4e-6 on f in [-0.5, 0.5]; avoids the MUFU pipe entirely.
__device__ __forceinline__ float fexp(float x) {
    float t = x * 1.4426950408889634f;
    t = fminf(fmaxf(t, -126.0f), 126.0f);
    float r = t + 12582912.0f;                       // round-to-nearest int in low bits
    int   n = __float_as_int(r) - 0x4B400000;        // integer part
    float f = t - (r - 12582912.0f);                 // frac in [-0.5, 0.5]
    float p = 1.3333558146428443e-3f;
    p = fmaf(p, f, 9.6181291076284772e-3f);
    p = fmaf(p, f, 5.5504108664821580e-2f);
    p = fmaf(p, f, 2.4022650695910072e-1f);
    p = fmaf(p, f, 6.9314718055994531e-1f);
    p = fmaf(p, f, 1.0f);
    return __int_as_float(__float_as_int(p) + (n << 23));
}

// ---------------------------------------------------------------------------
// Prep (merged): blocks 0..4095 split x; blocks 4096..8191 transpose+split W.
// ---------------------------------------------------------------------------
__global__ void prep_kernel(const float* __restrict__ x,
                            const float* __restrict__ wq, const float* __restrict__ wk,
                            const float* __restrict__ wv, const float* __restrict__ wo) {
    __shared__ float t[32][33];
    int bx = blockIdx.x, tid = threadIdx.x;
    if (bx < 4096) {
        size_t i4 = (size_t)bx * 256 + tid;
        float4 v = *(const float4*)&x[i4 * 4];
        __nv_bfloat16 h[4], l[4];
        split2(v.x, h[0], l[0]); split2(v.y, h[1], l[1]);
        split2(v.z, h[2], l[2]); split2(v.w, h[3], l[3]);
        *(uint2*)&g_xH[i4 * 4] = *(uint2*)h;
        *(uint2*)&g_xL[i4 * 4] = *(uint2*)l;
        return;
    }
    int idx = bx - 4096;
    int which = idx >> 10; idx &= 1023;
    const float* W = (which == 0) ? wq : (which == 1) ? wk : (which == 2) ? wv : wo;
    __nv_bfloat16* H = (which < 3) ? g_WtH + (size_t)which * DM * DM : g_WoTH;
    __nv_bfloat16* L = (which < 3) ? g_WtL + (size_t)which * DM * DM : g_WoTL;
    int x0 = (idx & 31) * 32, y0 = (idx >> 5) * 32;
    int tx = tid & 31, ty = tid >> 5;
    #pragma unroll
    for (int r = 0; r < 4; r++)
        t[ty + r * 8][tx] = W[(size_t)(y0 + ty + r * 8) * DM + x0 + tx];
    __syncthreads();
    #pragma unroll
    for (int r = 0; r < 4; r++) {
        float v = t[tx][ty + r * 8];
        __nv_bfloat16 h, l; split2(v, h, l);
        size_t dst = (size_t)(x0 + ty + r * 8) * DM + y0 + tx;
        H[dst] = h; L[dst] = l;
    }
}

// ---------------------------------------------------------------------------
// Projection GEMM mainloop: 2-stage cp.async double-buffered pipeline.
// ---------------------------------------------------------------------------
#define PS_AH 0
#define PS_AL 18432
#define PS_BH 36864
#define PS_BL 55296
#define PS_STAGE 73728
#define PROJ_SMEM (2 * PS_STAGE)

__device__ __forceinline__ void proj_prefetch(uint32_t sbs,
    const __nv_bfloat16* __restrict__ Ah, const __nv_bfloat16* __restrict__ Al,
    const __nv_bfloat16* __restrict__ Bh, const __nv_bfloat16* __restrict__ Bl,
    int m0, int n0, int k0, int tid) {
    #pragma unroll
    for (int e = 0; e < 4; e++) {
        int i = tid + e * 256;
        int row = i >> 3, cc = i & 7;
        size_t ga = (size_t)(m0 + row) * DM + k0 + cc * 8;
        size_t gb = (size_t)(n0 + row) * DM + k0 + cc * 8;
        uint32_t so = sbs + row * 144 + cc * 16;
        CPA16(so + PS_AH, Ah + ga);
        CPA16(so + PS_AL, Al + ga);
        CPA16(so + PS_BH, Bh + gb);
        CPA16(so + PS_BL, Bl + gb);
    }
}

__device__ __forceinline__ void gemm_ml(char* smem,
    const __nv_bfloat16* __restrict__ Ah, const __nv_bfloat16* __restrict__ Al,
    const __nv_bfloat16* __restrict__ Bh, const __nv_bfloat16* __restrict__ Bl,
    int m0, int n0, float (&c)[2][8][4]) {
    uint32_t sb0 = smem_u32(smem);
    int tid = threadIdx.x, lane = tid & 31, w = tid >> 5;
    int wm = (w >> 1) * 32, wn = (w & 1) * 64;

    proj_prefetch(sb0, Ah, Al, Bh, Bl, m0, n0, 0, tid);
    CPA_COMMIT();

    for (int s = 0; s < 16; s++) {
        if (s + 1 < 16) {
            proj_prefetch(sb0 + ((s + 1) & 1) * PS_STAGE, Ah, Al, Bh, Bl,
                          m0, n0, (s + 1) * 64, tid);
            CPA_COMMIT();
            CPA_WAIT1();
        } else {
            CPA_WAIT0();
        }
        __syncthreads();
        uint32_t sb = sb0 + (s & 1) * PS_STAGE;
        #pragma unroll
        for (int ks = 0; ks < 64; ks += 16) {
            uint32_t ah[2][4], al[2][4], bhf[8][2], blf[8][2];
            #pragma unroll
            for (int mt = 0; mt < 2; mt++) {
                uint32_t ad = sb + PS_AH + (uint32_t)(wm + mt * 16 + (lane & 15)) * 144
                            + (ks + (lane >> 4) * 8) * 2;
                ldsm4(ah[mt], ad);
                ldsm4(al[mt], ad + (PS_AL - PS_AH));
            }
            #pragma unroll
            for (int nt2 = 0; nt2 < 4; nt2++) {
                uint32_t bd = sb + PS_BH
                            + (uint32_t)(wn + nt2 * 16 + ((lane >> 4) << 3) + (lane & 7)) * 144
                            + (ks + ((lane >> 3) & 1) * 8) * 2;
                uint32_t t[4];
                ldsm4(t, bd);
                bhf[nt2*2][0]=t[0]; bhf[nt2*2][1]=t[1]; bhf[nt2*2+1][0]=t[2]; bhf[nt2*2+1][1]=t[3];
                ldsm4(t, bd + (PS_BL - PS_BH));
                blf[nt2*2][0]=t[0]; blf[nt2*2][1]=t[1]; blf[nt2*2+1][0]=t[2]; blf[nt2*2+1][1]=t[3];
            }
            #pragma unroll
            for (int mt = 0; mt < 2; mt++)
                #pragma unroll
                for (int nt = 0; nt < 8; nt++) {
                    mma16816(c[mt][nt], ah[mt], bhf[nt]);
                    mma16816(c[mt][nt], ah[mt], blf[nt]);
                    mma16816(c[mt][nt], al[mt], bhf[nt]);
                }
        }
        __syncthreads();
    }
}

// ---------------------------------------------------------------------------
// QKV projection
// ---------------------------------------------------------------------------
__global__ void __launch_bounds__(256, 1) proj_qkv_kernel(
    const float* __restrict__ bq, const float* __restrict__ bk, const float* __restrict__ bv) {
    extern __shared__ char smem[];
    int n0 = blockIdx.x * 128;
    int m0 = blockIdx.y * 128;
    float c[2][8][4] = {};
    gemm_ml(smem, g_xH, g_xL, g_WtH, g_WtL, m0, n0, c);

    int tid = threadIdx.x, lane = tid & 31, w = tid >> 5;
    int wm = (w >> 1) * 32, wn = (w & 1) * 64;
    int gid = lane >> 2, tid4 = lane & 3;
    int j = n0 >> 10, nb = n0 & 1023;
    const float* bias = (j == 0) ? bq : (j == 1) ? bk : bv;
    float scale = (j == 0) ? 0.125f : 1.0f;
    __nv_bfloat16* dH = (j == 0) ? g_QH : g_KH;
    __nv_bfloat16* dL = (j == 0) ? g_QL : g_KL;

    #pragma unroll
    for (int mt = 0; mt < 2; mt++)
        #pragma unroll
        for (int rh = 0; rh < 2; rh++) {
            int m = m0 + wm + mt * 16 + rh * 8 + gid;
            int b = m >> 11, s2 = m & (SEQ - 1);
            #pragma unroll
            for (int nt = 0; nt < 8; nt++) {
                int nl = nb + wn + nt * 8 + tid4 * 2;
                float v0 = (c[mt][nt][rh * 2 + 0] + bias[nl]) * scale;
                float v1 = (c[mt][nt][rh * 2 + 1] + bias[nl + 1]) * scale;
                __nv_bfloat16 h0, l0, h1, l1;
                split2(v0, h0, l0); split2(v1, h1, l1);
                int hh = nl >> 6, d = nl & 63;
                if (j < 2) {
                    size_t dst = (((size_t)(b * NH + hh)) * SEQ + s2) * DH + d;
                    *(uint32_t*)&dH[dst] = pack2(h0, h1);
                    *(uint32_t*)&dL[dst] = pack2(l0, l1);
                } else {
                    size_t dst = (((size_t)(b * NH + hh)) * DH + d) * SEQ + s2;
                    g_VtH[dst] = h0; g_VtH[dst + SEQ] = h1;
                    g_VtL[dst] = l0; g_VtL[dst + SEQ] = l1;
                }
            }
        }
}

// ---------------------------------------------------------------------------
// Output projection (standalone)
// ---------------------------------------------------------------------------
__global__ void __launch_bounds__(256, 1) proj_o_kernel(
    const float* __restrict__ bo, float* __restrict__ out) {
    extern __shared__ char smem[];
    int n0 = blockIdx.x * 128;
    int m0 = blockIdx.y * 128;
    float c[2][8][4] = {};
    gemm_ml(smem, g_attH, g_attL, g_WoTH, g_WoTL, m0, n0, c);

    int tid = threadIdx.x, lane = tid & 31, w = tid >> 5;
    int wm = (w >> 1) * 32, wn = (w & 1) * 64;
    int gid = lane >> 2, tid4 = lane & 3;

    #pragma unroll
    for (int mt = 0; mt < 2; mt++)
        #pragma unroll
        for (int rh = 0; rh < 2; rh++) {
            int m = m0 + wm + mt * 16 + rh * 8 + gid;
            #pragma unroll
            for (int nt = 0; nt < 8; nt++) {
                int n = n0 + wn + nt * 8 + tid4 * 2;
                float2 o;
                o.x = c[mt][nt][rh * 2 + 0] + bo[n];
                o.y = c[mt][nt][rh * 2 + 1] + bo[n + 1];
                *(float2*)&out[(size_t)m * DM + n] = o;
            }
        }
}

// ---------------------------------------------------------------------------
// Attention (R12 winner, __expf -> FMA-pipe fexp):
// 256 threads, q-tile 64, warp m16 x n64 (4m x 2n), register-E, occ 2,
// staggered cp.async K/V prefetch.
// ---------------------------------------------------------------------------
#define AT_QH 0
#define AT_QL 9216
#define AT_KH 18432
#define AT_KL 36864
#define AT_VH 55296
#define AT_VL 72704
#define AT_RED 90112
#define AT_RINV 90624
#define ATTN_SMEM 90880

__device__ __forceinline__ void attn_load_K(uint32_t sb, int bh, int kt, int tid) {
    #pragma unroll
    for (int e = 0; e < 4; e++) {
        int i = tid + e * 256;
        int row = i >> 3, c = i & 7;
        size_t g = ((size_t)bh * SEQ + kt * 128 + row) * DH + c * 8;
        uint32_t so = sb + AT_KH + row * 144 + c * 16;
        CPA16(so, g_KH + g);
        CPA16(so + (AT_KL - AT_KH), g_KL + g);
    }
}
__device__ __forceinline__ void attn_load_V(uint32_t sb, int bh, int kt, int tid) {
    #pragma unroll
    for (int e = 0; e < 4; e++) {
        int i = tid + e * 256;
        int row = i >> 4, c = i & 15;
        size_t g = ((size_t)bh * DH + row) * SEQ + kt * 128 + c * 8;
        uint32_t so = sb + AT_VH + row * 272 + c * 16;
        CPA16(so, g_VtH + g);
        CPA16(so + (AT_VL - AT_VH), g_VtL + g);
    }
}

__global__ void __launch_bounds__(256, 2) attn_tc_kernel(float* __restrict__ weights) {
    extern __shared__ char smem[];
    uint32_t sb = smem_u32(smem);
    int tid = threadIdx.x, lane = tid & 31, w = tid >> 5;
    int wg = w >> 1;
    int wm = wg * 16;
    int wn = (w & 1) * 64;
    int gid = lane >> 2, tid4 = lane & 3;
    int bh = blockIdx.y, q0 = blockIdx.x * 64;

    // preamble: Q + K(0) as group A, V(0) as group B
    #pragma unroll
    for (int e = 0; e < 2; e++) {
        int i = tid + e * 256;
        int row = i >> 3, c = i & 7;
        size_t g = ((size_t)bh * SEQ + q0 + row) * DH + c * 8;
        uint32_t so = sb + AT_QH + row * 144 + c * 16;
        CPA16(so, g_QH + g);
        CPA16(so + (AT_QL - AT_QH), g_QL + g);
    }
    attn_load_K(sb, bh, 0, tid);
    CPA_COMMIT();
    attn_load_V(sb, bh, 0, tid);
    CPA_COMMIT();

    float* wbase = weights + (size_t)bh * SEQ * SEQ;
    float pv[8][4] = {};
    float rsum[2] = {};

    for (int kt = 0; kt < SEQ / 128; kt++) {
        CPA_WAIT1();                 // Q + K(kt) arrived (V(kt) may pend)
        __syncthreads();

        // ---- S = Q K^T (scale pre-folded into Q) ----
        float s[8][4] = {};
        #pragma unroll
        for (int ks = 0; ks < 64; ks += 16) {
            uint32_t ah[4], al[4], bhf[8][2], blf[8][2];
            uint32_t ad = sb + AT_QH + (uint32_t)(wm + (lane & 15)) * 144
                        + (ks + (lane >> 4) * 8) * 2;
            ldsm4(ah, ad);
            ldsm4(al, ad + (AT_QL - AT_QH));
            #pragma unroll
            for (int nt2 = 0; nt2 < 4; nt2++) {
                uint32_t bd = sb + AT_KH
                            + (uint32_t)(wn + nt2 * 16 + ((lane >> 4) << 3) + (lane & 7)) * 144
                            + (ks + ((lane >> 3) & 1) * 8) * 2;
                uint32_t t[4];
                ldsm4(t, bd);
                bhf[nt2*2][0]=t[0]; bhf[nt2*2][1]=t[1]; bhf[nt2*2+1][0]=t[2]; bhf[nt2*2+1][1]=t[3];
                ldsm4(t, bd + (AT_KL - AT_KH));
                blf[nt2*2][0]=t[0]; blf[nt2*2][1]=t[1]; blf[nt2*2+1][0]=t[2]; blf[nt2*2+1][1]=t[3];
            }
            #pragma unroll
            for (int nt = 0; nt < 8; nt++) {
                mma16816(s[nt], ah, bhf[nt]);
                mma16816(s[nt], ah, blf[nt]);
                mma16816(s[nt], al, bhf[nt]);
            }
        }
        __syncthreads();             // all warps done reading K smem
        if (kt + 1 < SEQ / 128) {
            attn_load_K(sb, bh, kt + 1, tid);   // GK(kt+1): lands under exp+PV
            CPA_COMMIT();
        }

        // ---- exp (FMA pipe), rowsum, unnormalized weights store ----
        int row0 = q0 + wm + gid;
        #pragma unroll
        for (int nt = 0; nt < 8; nt++) {
            s[nt][0] = fexp(s[nt][0]);
            s[nt][1] = fexp(s[nt][1]);
            s[nt][2] = fexp(s[nt][2]);
            s[nt][3] = fexp(s[nt][3]);
            rsum[0] += s[nt][0] + s[nt][1];
            rsum[1] += s[nt][2] + s[nt][3];
            int col = kt * 128 + wn + nt * 8 + tid4 * 2;
            *(float2*)&wbase[(size_t)row0 * SEQ + col]       = make_float2(s[nt][0], s[nt][1]);
            *(float2*)&wbase[(size_t)(row0 + 8) * SEQ + col] = make_float2(s[nt][2], s[nt][3]);
        }

        if (kt + 1 < SEQ / 128) { CPA_WAIT1(); } else { CPA_WAIT0(); }  // V(kt) arrived
        __syncthreads();

        // ---- pv += E(this warp's k-slice) x V ----
        #pragma unroll
        for (int j = 0; j < 4; j++) {
            uint32_t eh[4], el[4];
            eh[0] = pack2f (s[2*j][0],   s[2*j][1]);
            eh[1] = pack2f (s[2*j][2],   s[2*j][3]);
            eh[2] = pack2f (s[2*j+1][0], s[2*j+1][1]);
            eh[3] = pack2f (s[2*j+1][2], s[2*j+1][3]);
            el[0] = pack2lo(s[2*j][0],   s[2*j][1]);
            el[1] = pack2lo(s[2*j][2],   s[2*j][3]);
            el[2] = pack2lo(s[2*j+1][0], s[2*j+1][1]);
            el[3] = pack2lo(s[2*j+1][2], s[2*j+1][3]);

            uint32_t vh[8][2], vl[8][2];
            #pragma unroll
            for (int dt2 = 0; dt2 < 4; dt2++) {
                uint32_t bd = sb + AT_VH
                            + (uint32_t)(dt2 * 16 + ((lane >> 4) << 3) + (lane & 7)) * 272
                            + (wn + j * 16 + ((lane >> 3) & 1) * 8) * 2;
                uint32_t t[4];
                ldsm4(t, bd);
                vh[dt2*2][0]=t[0]; vh[dt2*2][1]=t[1]; vh[dt2*2+1][0]=t[2]; vh[dt2*2+1][1]=t[3];
                ldsm4(t, bd + (AT_VL - AT_VH));
                vl[dt2*2][0]=t[0]; vl[dt2*2][1]=t[1]; vl[dt2*2+1][0]=t[2]; vl[dt2*2+1][1]=t[3];
            }
            #pragma unroll
            for (int nt = 0; nt < 8; nt++) {
                mma16816(pv[nt], eh, vh[nt]);
                mma16816(pv[nt], eh, vl[nt]);
                mma16816(pv[nt], el, vh[nt]);
            }
        }
        __syncthreads();             // all warps done reading V smem
        if (kt + 1 < SEQ / 128) {
            attn_load_V(sb, bh, kt + 1, tid);   // GV(kt+1): lands under next S+exp
            CPA_COMMIT();
        }
    }
    __syncthreads();

    // ---- rowsum reduce ----
    float* red   = (float*)(smem + AT_RED);
    float* rinvs = (float*)(smem + AT_RINV);
    #pragma unroll
    for (int i = 0; i < 2; i++) {
        rsum[i] += __shfl_xor_sync(0xFFFFFFFFu, rsum[i], 1);
        rsum[i] += __shfl_xor_sync(0xFFFFFFFFu, rsum[i], 2);
    }
    if (tid4 == 0) {
        red[(wm + 0 + gid) * 2 + (w & 1)] = rsum[0];
        red[(wm + 8 + gid) * 2 + (w & 1)] = rsum[1];
    }
    __syncthreads();
    if (tid < 64) {
        float ri = 1.0f / (red[tid * 2] + red[tid * 2 + 1]);
        rinvs[tid] = ri;
        g_rinv[(size_t)bh * SEQ + q0 + tid] = ri;
    }

    // ---- cross-warp PV add ----
    float* xch = (float*)(smem + AT_KH);
    if (w & 1) {
        #pragma unroll
        for (int nt = 0; nt < 8; nt++)
            #pragma unroll
            for (int i = 0; i < 4; i++)
                xch[(wg * 32 + lane) * 32 + nt * 4 + i] = pv[nt][i];
    }
    __syncthreads();
    if (!(w & 1)) {
        #pragma unroll
        for (int nt = 0; nt < 8; nt++)
            #pragma unroll
            for (int i = 0; i < 4; i++)
                pv[nt][i] += xch[(wg * 32 + lane) * 32 + nt * 4 + i];

        int b = bh >> 4, h = bh & 15;
        #pragma unroll
        for (int rh = 0; rh < 2; rh++) {
            int row = wm + rh * 8 + gid;
            float ri = rinvs[row];
            #pragma unroll
            for (int nt = 0; nt < 8; nt++) {
                float v0 = pv[nt][rh * 2 + 0] * ri;
                float v1 = pv[nt][rh * 2 + 1] * ri;
                int d = nt * 8 + tid4 * 2;
                __nv_bfloat16 h0, l0, h1, l1;
                split2(v0, h0, l0); split2(v1, h1, l1);
                size_t dst = ((size_t)(b * SEQ + q0 + row)) * DM + h * DH + d;
                *(uint32_t*)&g_attH[dst] = pack2(h0, h1);
                *(uint32_t*)&g_attL[dst] = pack2(l0, l1);
            }
        }
    }
}

// ---------------------------------------------------------------------------
// Normalize weights in place (streaming)
// ---------------------------------------------------------------------------
__global__ void norm_kernel(float* __restrict__ w) {
    size_t f4 = (size_t)blockIdx.x * blockDim.x + threadIdx.x;
    size_t fidx = f4 * 4;
    int rowi = (int)(fidx >> 11);
    float r = g_rinv[rowi];
    float4 v = *(float4*)&w[fidx];
    v.x *= r; v.y *= r; v.z *= r; v.w *= r;
    *(float4*)&w[fidx] = v;
}

// ---------------------------------------------------------------------------
extern "C" void kernel_launch(void* const* d_in, const int* in_sizes, int n_in,
                              void* d_out, int out_size) {
    const float* x  = (const float*)d_in[0];
    const float* wq = (const float*)d_in[1];
    const float* bq = (const float*)d_in[2];
    const float* wk = (const float*)d_in[3];
    const float* bk = (const float*)d_in[4];
    const float* wv = (const float*)d_in[5];
    const float* bv = (const float*)d_in[6];
    const float* wo = (const float*)d_in[7];
    const float* bo = (const float*)d_in[8];

    float* out     = (float*)d_out;
    float* weights = out + (size_t)M_TOT * DM;

    static cudaStream_t s2 = nullptr;
    static cudaEvent_t evFork = nullptr, evJoin = nullptr;
    if (!s2) {
        cudaStreamCreateWithFlags(&s2, cudaStreamNonBlocking);
        cudaEventCreateWithFlags(&evFork, cudaEventDisableTiming);
        cudaEventCreateWithFlags(&evJoin, cudaEventDisableTiming);
        cudaFuncSetAttribute(proj_qkv_kernel, cudaFuncAttributeMaxDynamicSharedMemorySize, PROJ_SMEM);
        cudaFuncSetAttribute(proj_o_kernel,   cudaFuncAttributeMaxDynamicSharedMemorySize, PROJ_SMEM);
        cudaFuncSetAttribute(attn_tc_kernel,  cudaFuncAttributeMaxDynamicSharedMemorySize, ATTN_SMEM);
    }

    prep_kernel<<<8192, 256>>>(x, wq, wk, wv, wo);

    proj_qkv_kernel<<<dim3(3 * DM / 128, M_TOT / 128), 256, PROJ_SMEM>>>(bq, bk, bv);

    attn_tc_kernel<<<dim3(SEQ / 64, BH_TOT), 256, ATTN_SMEM>>>(weights);

    // Fork: norm (DRAM-bound) concurrent with proj_o (tensor-bound)
    cudaEventRecord(evFork, 0);
    cudaStreamWaitEvent(s2, evFork, 0);

    size_t nf4 = (size_t)BH_TOT * SEQ * SEQ / 4;
    norm_kernel<<<(unsigned)(nf4 / 256), 256, 0, s2>>>(weights);

    proj_o_kernel<<<dim3(DM / 128, M_TOT / 128), 256, PROJ_SMEM>>>(bo, out);

    cudaEventRecord(evJoin, s2);
    cudaStreamWaitEvent(0, evJoin, 0);
}

// round 15
// speedup vs baseline: 1.0411x; 1.0411x over previous
#include <cuda_runtime.h>
#include <cuda_bf16.h>
#include <cstdint>

#define BATCH 2
#define SEQ   2048
#define DM    1024
#define NH    16
#define DH    64
#define M_TOT (BATCH*SEQ)   // 4096
#define BH_TOT (BATCH*NH)   // 32

// ---------------------------------------------------------------------------
// Scratch (__device__ globals; allocation-free rule)
// ---------------------------------------------------------------------------
__device__ __nv_bfloat16 g_xH[M_TOT*DM],  g_xL[M_TOT*DM];
__device__ __nv_bfloat16 g_WtH[3*DM*DM],  g_WtL[3*DM*DM];      // [n][k], q|k|v
__device__ __nv_bfloat16 g_WoTH[DM*DM],   g_WoTL[DM*DM];       // [n][k]
__device__ __nv_bfloat16 g_QH[BH_TOT*SEQ*DH], g_QL[BH_TOT*SEQ*DH];
__device__ __nv_bfloat16 g_KH[BH_TOT*SEQ*DH], g_KL[BH_TOT*SEQ*DH];
__device__ __nv_bfloat16 g_VtH[BH_TOT*DH*SEQ], g_VtL[BH_TOT*DH*SEQ]; // [bh][d][s]
__device__ __nv_bfloat16 g_attH[M_TOT*DM], g_attL[M_TOT*DM];
__device__ float g_rinv[BH_TOT*SEQ];

// ---------------------------------------------------------------------------
// Helpers
// ---------------------------------------------------------------------------
__device__ __forceinline__ uint32_t smem_u32(const void* p) {
    uint32_t a;
    asm("{ .reg .u64 t; cvta.to.shared.u64 t, %1; cvt.u32.u64 %0, t; }" : "=r"(a) : "l"(p));
    return a;
}
__device__ __forceinline__ void ldsm4(uint32_t* r, uint32_t a) {
    asm volatile("ldmatrix.sync.aligned.m8n8.x4.shared.b16 {%0,%1,%2,%3}, [%4];"
        : "=r"(r[0]), "=r"(r[1]), "=r"(r[2]), "=r"(r[3]) : "r"(a));
}
__device__ __forceinline__ void mma16816(float* d, const uint32_t* a, const uint32_t* b) {
    asm volatile("mma.sync.aligned.m16n8k16.row.col.f32.bf16.bf16.f32 "
        "{%0,%1,%2,%3},{%4,%5,%6,%7},{%8,%9},{%0,%1,%2,%3};"
        : "+f"(d[0]), "+f"(d[1]), "+f"(d[2]), "+f"(d[3])
        : "r"(a[0]), "r"(a[1]), "r"(a[2]), "r"(a[3]), "r"(b[0]), "r"(b[1]));
}
#define CPA16(s, g) asm volatile("cp.async.ca.shared.global [%0], [%1], 16;" :: "r"(s), "l"(g) : "memory")
#define CPA_COMMIT() asm volatile("cp.async.commit_group;" ::: "memory")
#define CPA_WAIT0()  asm volatile("cp.async.wait_group 0;" ::: "memory")
#define CPA_WAIT1()  asm volatile("cp.async.wait_group 1;" ::: "memory")

__device__ __forceinline__ void split2(float v, __nv_bfloat16& h, __nv_bfloat16& l) {
    h = __float2bfloat16(v);
    l = __float2bfloat16(v - __bfloat162float(h));
}
__device__ __forceinline__ uint32_t pack2(__nv_bfloat16 a, __nv_bfloat16 b) {
    __nv_bfloat162 t; t.x = a; t.y = b;
    return *reinterpret_cast<uint32_t*>(&t);
}
__device__ __forceinline__ uint32_t pack2f(float a, float b) {
    __nv_bfloat162 t; t.x = __float2bfloat16(a); t.y = __float2bfloat16(b);
    return *reinterpret_cast<uint32_t*>(&t);
}
__device__ __forceinline__ uint32_t pack2lo(float a, float b) {
    __nv_bfloat16 ha = __float2bfloat16(a), hb = __float2bfloat16(b);
    __nv_bfloat162 t;
    t.x = __float2bfloat16(a - __bfloat162float(ha));
    t.y = __float2bfloat16(b - __bfloat162float(hb));
    return *reinterpret_cast<uint32_t*>(&t);
}

// ---------------------------------------------------------------------------
// Prep (merged): blocks 0..4095 split x; blocks 4096..8191 transpose+split W.
// ---------------------------------------------------------------------------
__global__ void prep_kernel(const float* __restrict__ x,
                            const float* __restrict__ wq, const float* __restrict__ wk,
                            const float* __restrict__ wv, const float* __restrict__ wo) {
    __shared__ float t[32][33];
    int bx = blockIdx.x, tid = threadIdx.x;
    if (bx < 4096) {
        size_t i4 = (size_t)bx * 256 + tid;
        float4 v = *(const float4*)&x[i4 * 4];
        __nv_bfloat16 h[4], l[4];
        split2(v.x, h[0], l[0]); split2(v.y, h[1], l[1]);
        split2(v.z, h[2], l[2]); split2(v.w, h[3], l[3]);
        *(uint2*)&g_xH[i4 * 4] = *(uint2*)h;
        *(uint2*)&g_xL[i4 * 4] = *(uint2*)l;
        return;
    }
    int idx = bx - 4096;
    int which = idx >> 10; idx &= 1023;
    const float* W = (which == 0) ? wq : (which == 1) ? wk : (which == 2) ? wv : wo;
    __nv_bfloat16* H = (which < 3) ? g_WtH + (size_t)which * DM * DM : g_WoTH;
    __nv_bfloat16* L = (which < 3) ? g_WtL + (size_t)which * DM * DM : g_WoTL;
    int x0 = (idx & 31) * 32, y0 = (idx >> 5) * 32;
    int tx = tid & 31, ty = tid >> 5;
    #pragma unroll
    for (int r = 0; r < 4; r++)
        t[ty + r * 8][tx] = W[(size_t)(y0 + ty + r * 8) * DM + x0 + tx];
    __syncthreads();
    #pragma unroll
    for (int r = 0; r < 4; r++) {
        float v = t[tx][ty + r * 8];
        __nv_bfloat16 h, l; split2(v, h, l);
        size_t dst = (size_t)(x0 + ty + r * 8) * DM + y0 + tx;
        H[dst] = h; L[dst] = l;
    }
}

// ---------------------------------------------------------------------------
// Shared 128x128 GEMM mainloop (used by proj_o): 2-stage cp.async pipeline.
// ---------------------------------------------------------------------------
#define PS_AH 0
#define PS_AL 18432
#define PS_BH 36864
#define PS_BL 55296
#define PS_STAGE 73728
#define PROJ_SMEM (2 * PS_STAGE)

__device__ __forceinline__ void proj_prefetch(uint32_t sbs,
    const __nv_bfloat16* __restrict__ Ah, const __nv_bfloat16* __restrict__ Al,
    const __nv_bfloat16* __restrict__ Bh, const __nv_bfloat16* __restrict__ Bl,
    int m0, int n0, int k0, int tid) {
    #pragma unroll
    for (int e = 0; e < 4; e++) {
        int i = tid + e * 256;
        int row = i >> 3, cc = i & 7;
        size_t ga = (size_t)(m0 + row) * DM + k0 + cc * 8;
        size_t gb = (size_t)(n0 + row) * DM + k0 + cc * 8;
        uint32_t so = sbs + row * 144 + cc * 16;
        CPA16(so + PS_AH, Ah + ga);
        CPA16(so + PS_AL, Al + ga);
        CPA16(so + PS_BH, Bh + gb);
        CPA16(so + PS_BL, Bl + gb);
    }
}

__device__ __forceinline__ void gemm_ml(char* smem,
    const __nv_bfloat16* __restrict__ Ah, const __nv_bfloat16* __restrict__ Al,
    const __nv_bfloat16* __restrict__ Bh, const __nv_bfloat16* __restrict__ Bl,
    int m0, int n0, float (&c)[2][8][4]) {
    uint32_t sb0 = smem_u32(smem);
    int tid = threadIdx.x, lane = tid & 31, w = tid >> 5;
    int wm = (w >> 1) * 32, wn = (w & 1) * 64;

    proj_prefetch(sb0, Ah, Al, Bh, Bl, m0, n0, 0, tid);
    CPA_COMMIT();

    for (int s = 0; s < 16; s++) {
        if (s + 1 < 16) {
            proj_prefetch(sb0 + ((s + 1) & 1) * PS_STAGE, Ah, Al, Bh, Bl,
                          m0, n0, (s + 1) * 64, tid);
            CPA_COMMIT();
            CPA_WAIT1();
        } else {
            CPA_WAIT0();
        }
        __syncthreads();
        uint32_t sb = sb0 + (s & 1) * PS_STAGE;
        #pragma unroll
        for (int ks = 0; ks < 64; ks += 16) {
            uint32_t ah[2][4], al[2][4], bhf[8][2], blf[8][2];
            #pragma unroll
            for (int mt = 0; mt < 2; mt++) {
                uint32_t ad = sb + PS_AH + (uint32_t)(wm + mt * 16 + (lane & 15)) * 144
                            + (ks + (lane >> 4) * 8) * 2;
                ldsm4(ah[mt], ad);
                ldsm4(al[mt], ad + (PS_AL - PS_AH));
            }
            #pragma unroll
            for (int nt2 = 0; nt2 < 4; nt2++) {
                uint32_t bd = sb + PS_BH
                            + (uint32_t)(wn + nt2 * 16 + ((lane >> 4) << 3) + (lane & 7)) * 144
                            + (ks + ((lane >> 3) & 1) * 8) * 2;
                uint32_t t[4];
                ldsm4(t, bd);
                bhf[nt2*2][0]=t[0]; bhf[nt2*2][1]=t[1]; bhf[nt2*2+1][0]=t[2]; bhf[nt2*2+1][1]=t[3];
                ldsm4(t, bd + (PS_BL - PS_BH));
                blf[nt2*2][0]=t[0]; blf[nt2*2][1]=t[1]; blf[nt2*2+1][0]=t[2]; blf[nt2*2+1][1]=t[3];
            }
            #pragma unroll
            for (int mt = 0; mt < 2; mt++)
                #pragma unroll
                for (int nt = 0; nt < 8; nt++) {
                    mma16816(c[mt][nt], ah[mt], bhf[nt]);
                    mma16816(c[mt][nt], ah[mt], blf[nt]);
                    mma16816(c[mt][nt], al[mt], bhf[nt]);
                }
        }
        __syncthreads();
    }
}

// ---------------------------------------------------------------------------
// QKV projection: 128x256 tile (A loaded once per TWO n-tiles).
// smem 2 x 108KB stages; 256 thr = 8 warps (4m x 2n), warp 32x128.
// ---------------------------------------------------------------------------
#define QS_AH 0
#define QS_AL 18432
#define QS_BH 36864
#define QS_BL 73728
#define QS_STAGE 110592
#define QKV_SMEM (2 * QS_STAGE)   // 221184

__device__ __forceinline__ void qkv_prefetch(uint32_t sbs, int m0, int n0, int k0, int tid) {
    #pragma unroll
    for (int e = 0; e < 4; e++) {
        int i = tid + e * 256;
        int row = i >> 3, cc = i & 7;
        size_t ga = (size_t)(m0 + row) * DM + k0 + cc * 8;
        uint32_t so = sbs + row * 144 + cc * 16;
        CPA16(so + QS_AH, g_xH + ga);
        CPA16(so + QS_AL, g_xL + ga);
    }
    #pragma unroll
    for (int e = 0; e < 8; e++) {
        int i = tid + e * 256;
        int row = i >> 3, cc = i & 7;
        size_t gb = (size_t)(n0 + row) * DM + k0 + cc * 8;
        uint32_t so = sbs + row * 144 + cc * 16;
        CPA16(so + QS_BH, g_WtH + gb);
        CPA16(so + QS_BL, g_WtL + gb);
    }
}

__global__ void __launch_bounds__(256, 1) proj_qkv_kernel(
    const float* __restrict__ bq, const float* __restrict__ bk, const float* __restrict__ bv) {
    extern __shared__ char smem[];
    uint32_t sb0 = smem_u32(smem);
    int tid = threadIdx.x, lane = tid & 31, w = tid >> 5;
    int wm = (w >> 1) * 32, wn = (w & 1) * 128;
    int n0 = blockIdx.x * 256;   // 0..2816 (12 tiles over 3072)
    int m0 = blockIdx.y * 128;

    float c[2][16][4] = {};

    qkv_prefetch(sb0, m0, n0, 0, tid);
    CPA_COMMIT();

    for (int s = 0; s < 16; s++) {
        if (s + 1 < 16) {
            qkv_prefetch(sb0 + ((s + 1) & 1) * QS_STAGE, m0, n0, (s + 1) * 64, tid);
            CPA_COMMIT();
            CPA_WAIT1();
        } else {
            CPA_WAIT0();
        }
        __syncthreads();
        uint32_t sb = sb0 + (s & 1) * QS_STAGE;
        #pragma unroll
        for (int ks = 0; ks < 64; ks += 16) {
            uint32_t ah[2][4], al[2][4];
            #pragma unroll
            for (int mt = 0; mt < 2; mt++) {
                uint32_t ad = sb + QS_AH + (uint32_t)(wm + mt * 16 + (lane & 15)) * 144
                            + (ks + (lane >> 4) * 8) * 2;
                ldsm4(ah[mt], ad);
                ldsm4(al[mt], ad + (QS_AL - QS_AH));
            }
            #pragma unroll
            for (int half = 0; half < 2; half++) {
                uint32_t bhf[8][2], blf[8][2];
                #pragma unroll
                for (int nt2 = 0; nt2 < 4; nt2++) {
                    uint32_t bd = sb + QS_BH
                                + (uint32_t)(wn + half * 64 + nt2 * 16
                                             + ((lane >> 4) << 3) + (lane & 7)) * 144
                                + (ks + ((lane >> 3) & 1) * 8) * 2;
                    uint32_t t[4];
                    ldsm4(t, bd);
                    bhf[nt2*2][0]=t[0]; bhf[nt2*2][1]=t[1]; bhf[nt2*2+1][0]=t[2]; bhf[nt2*2+1][1]=t[3];
                    ldsm4(t, bd + (QS_BL - QS_BH));
                    blf[nt2*2][0]=t[0]; blf[nt2*2][1]=t[1]; blf[nt2*2+1][0]=t[2]; blf[nt2*2+1][1]=t[3];
                }
                #pragma unroll
                for (int mt = 0; mt < 2; mt++)
                    #pragma unroll
                    for (int nt = 0; nt < 8; nt++) {
                        mma16816(c[mt][half * 8 + nt], ah[mt], bhf[nt]);
                        mma16816(c[mt][half * 8 + nt], ah[mt], blf[nt]);
                        mma16816(c[mt][half * 8 + nt], al[mt], bhf[nt]);
                    }
            }
        }
        __syncthreads();
    }

    // epilogue (tile never crosses q/k/v boundary: 1024 % 256 == 0)
    int gid = lane >> 2, tid4 = lane & 3;
    int j = n0 >> 10, nb = n0 & 1023;
    const float* bias = (j == 0) ? bq : (j == 1) ? bk : bv;
    float scale = (j == 0) ? 0.125f : 1.0f;
    __nv_bfloat16* dH = (j == 0) ? g_QH : g_KH;
    __nv_bfloat16* dL = (j == 0) ? g_QL : g_KL;

    #pragma unroll
    for (int mt = 0; mt < 2; mt++)
        #pragma unroll
        for (int rh = 0; rh < 2; rh++) {
            int m = m0 + wm + mt * 16 + rh * 8 + gid;
            int b = m >> 11, s2 = m & (SEQ - 1);
            #pragma unroll
            for (int nt = 0; nt < 16; nt++) {
                int nl = nb + wn + nt * 8 + tid4 * 2;
                float v0 = (c[mt][nt][rh * 2 + 0] + bias[nl]) * scale;
                float v1 = (c[mt][nt][rh * 2 + 1] + bias[nl + 1]) * scale;
                __nv_bfloat16 h0, l0, h1, l1;
                split2(v0, h0, l0); split2(v1, h1, l1);
                int hh = nl >> 6, d = nl & 63;
                if (j < 2) {
                    size_t dst = (((size_t)(b * NH + hh)) * SEQ + s2) * DH + d;
                    *(uint32_t*)&dH[dst] = pack2(h0, h1);
                    *(uint32_t*)&dL[dst] = pack2(l0, l1);
                } else {
                    size_t dst = (((size_t)(b * NH + hh)) * DH + d) * SEQ + s2;
                    g_VtH[dst] = h0; g_VtH[dst + SEQ] = h1;
                    g_VtL[dst] = l0; g_VtL[dst + SEQ] = l1;
                }
            }
        }
}

// ---------------------------------------------------------------------------
// Output projection (standalone 128x128)
// ---------------------------------------------------------------------------
__global__ void __launch_bounds__(256, 1) proj_o_kernel(
    const float* __restrict__ bo, float* __restrict__ out) {
    extern __shared__ char smem[];
    int n0 = blockIdx.x * 128;
    int m0 = blockIdx.y * 128;
    float c[2][8][4] = {};
    gemm_ml(smem, g_attH, g_attL, g_WoTH, g_WoTL, m0, n0, c);

    int tid = threadIdx.x, lane = tid & 31, w = tid >> 5;
    int wm = (w >> 1) * 32, wn = (w & 1) * 64;
    int gid = lane >> 2, tid4 = lane & 3;

    #pragma unroll
    for (int mt = 0; mt < 2; mt++)
        #pragma unroll
        for (int rh = 0; rh < 2; rh++) {
            int m = m0 + wm + mt * 16 + rh * 8 + gid;
            #pragma unroll
            for (int nt = 0; nt < 8; nt++) {
                int n = n0 + wn + nt * 8 + tid4 * 2;
                float2 o;
                o.x = c[mt][nt][rh * 2 + 0] + bo[n];
                o.y = c[mt][nt][rh * 2 + 1] + bo[n + 1];
                *(float2*)&out[(size_t)m * DM + n] = o;
            }
        }
}

// ---------------------------------------------------------------------------
// Attention (R12 winner, verbatim): 256 threads, q-tile 64, warp m16 x n64,
// register-E, occ 2, staggered cp.async K/V prefetch, __expf.
// ---------------------------------------------------------------------------
#define AT_QH 0
#define AT_QL 9216
#define AT_KH 18432
#define AT_KL 36864
#define AT_VH 55296
#define AT_VL 72704
#define AT_RED 90112
#define AT_RINV 90624
#define ATTN_SMEM 90880

__device__ __forceinline__ void attn_load_K(uint32_t sb, int bh, int kt, int tid) {
    #pragma unroll
    for (int e = 0; e < 4; e++) {
        int i = tid + e * 256;
        int row = i >> 3, c = i & 7;
        size_t g = ((size_t)bh * SEQ + kt * 128 + row) * DH + c * 8;
        uint32_t so = sb + AT_KH + row * 144 + c * 16;
        CPA16(so, g_KH + g);
        CPA16(so + (AT_KL - AT_KH), g_KL + g);
    }
}
__device__ __forceinline__ void attn_load_V(uint32_t sb, int bh, int kt, int tid) {
    #pragma unroll
    for (int e = 0; e < 4; e++) {
        int i = tid + e * 256;
        int row = i >> 4, c = i & 15;
        size_t g = ((size_t)bh * DH + row) * SEQ + kt * 128 + c * 8;
        uint32_t so = sb + AT_VH + row * 272 + c * 16;
        CPA16(so, g_VtH + g);
        CPA16(so + (AT_VL - AT_VH), g_VtL + g);
    }
}

__global__ void __launch_bounds__(256, 2) attn_tc_kernel(float* __restrict__ weights) {
    extern __shared__ char smem[];
    uint32_t sb = smem_u32(smem);
    int tid = threadIdx.x, lane = tid & 31, w = tid >> 5;
    int wg = w >> 1;
    int wm = wg * 16;
    int wn = (w & 1) * 64;
    int gid = lane >> 2, tid4 = lane & 3;
    int bh = blockIdx.y, q0 = blockIdx.x * 64;

    // preamble: Q + K(0) as group A, V(0) as group B
    #pragma unroll
    for (int e = 0; e < 2; e++) {
        int i = tid + e * 256;
        int row = i >> 3, c = i & 7;
        size_t g = ((size_t)bh * SEQ + q0 + row) * DH + c * 8;
        uint32_t so = sb + AT_QH + row * 144 + c * 16;
        CPA16(so, g_QH + g);
        CPA16(so + (AT_QL - AT_QH), g_QL + g);
    }
    attn_load_K(sb, bh, 0, tid);
    CPA_COMMIT();
    attn_load_V(sb, bh, 0, tid);
    CPA_COMMIT();

    float* wbase = weights + (size_t)bh * SEQ * SEQ;
    float pv[8][4] = {};
    float rsum[2] = {};

    for (int kt = 0; kt < SEQ / 128; kt++) {
        CPA_WAIT1();                 // Q + K(kt) arrived (V(kt) may pend)
        __syncthreads();

        // ---- S = Q K^T (scale pre-folded into Q) ----
        float s[8][4] = {};
        #pragma unroll
        for (int ks = 0; ks < 64; ks += 16) {
            uint32_t ah[4], al[4], bhf[8][2], blf[8][2];
            uint32_t ad = sb + AT_QH + (uint32_t)(wm + (lane & 15)) * 144
                        + (ks + (lane >> 4) * 8) * 2;
            ldsm4(ah, ad);
            ldsm4(al, ad + (AT_QL - AT_QH));
            #pragma unroll
            for (int nt2 = 0; nt2 < 4; nt2++) {
                uint32_t bd = sb + AT_KH
                            + (uint32_t)(wn + nt2 * 16 + ((lane >> 4) << 3) + (lane & 7)) * 144
                            + (ks + ((lane >> 3) & 1) * 8) * 2;
                uint32_t t[4];
                ldsm4(t, bd);
                bhf[nt2*2][0]=t[0]; bhf[nt2*2][1]=t[1]; bhf[nt2*2+1][0]=t[2]; bhf[nt2*2+1][1]=t[3];
                ldsm4(t, bd + (AT_KL - AT_KH));
                blf[nt2*2][0]=t[0]; blf[nt2*2][1]=t[1]; blf[nt2*2+1][0]=t[2]; blf[nt2*2+1][1]=t[3];
            }
            #pragma unroll
            for (int nt = 0; nt < 8; nt++) {
                mma16816(s[nt], ah, bhf[nt]);
                mma16816(s[nt], ah, blf[nt]);
                mma16816(s[nt], al, bhf[nt]);
            }
        }
        __syncthreads();             // all warps done reading K smem
        if (kt + 1 < SEQ / 128) {
            attn_load_K(sb, bh, kt + 1, tid);   // GK(kt+1): lands under exp+PV
            CPA_COMMIT();
        }

        // ---- exp, rowsum, unnormalized weights store ----
        int row0 = q0 + wm + gid;
        #pragma unroll
        for (int nt = 0; nt < 8; nt++) {
            s[nt][0] = __expf(s[nt][0]);
            s[nt][1] = __expf(s[nt][1]);
            s[nt][2] = __expf(s[nt][2]);
            s[nt][3] = __expf(s[nt][3]);
            rsum[0] += s[nt][0] + s[nt][1];
            rsum[1] += s[nt][2] + s[nt][3];
            int col = kt * 128 + wn + nt * 8 + tid4 * 2;
            *(float2*)&wbase[(size_t)row0 * SEQ + col]       = make_float2(s[nt][0], s[nt][1]);
            *(float2*)&wbase[(size_t)(row0 + 8) * SEQ + col] = make_float2(s[nt][2], s[nt][3]);
        }

        if (kt + 1 < SEQ / 128) { CPA_WAIT1(); } else { CPA_WAIT0(); }  // V(kt) arrived
        __syncthreads();

        // ---- pv += E(this warp's k-slice) x V ----
        #pragma unroll
        for (int j = 0; j < 4; j++) {
            uint32_t eh[4], el[4];
            eh[0] = pack2f (s[2*j][0],   s[2*j][1]);
            eh[1] = pack2f (s[2*j][2],   s[2*j][3]);
            eh[2] = pack2f (s[2*j+1][0], s[2*j+1][1]);
            eh[3] = pack2f (s[2*j+1][2], s[2*j+1][3]);
            el[0] = pack2lo(s[2*j][0],   s[2*j][1]);
            el[1] = pack2lo(s[2*j][2],   s[2*j][3]);
            el[2] = pack2lo(s[2*j+1][0], s[2*j+1][1]);
            el[3] = pack2lo(s[2*j+1][2], s[2*j+1][3]);

            uint32_t vh[8][2], vl[8][2];
            #pragma unroll
            for (int dt2 = 0; dt2 < 4; dt2++) {
                uint32_t bd = sb + AT_VH
                            + (uint32_t)(dt2 * 16 + ((lane >> 4) << 3) + (lane & 7)) * 272
                            + (wn + j * 16 + ((lane >> 3) & 1) * 8) * 2;
                uint32_t t[4];
                ldsm4(t, bd);
                vh[dt2*2][0]=t[0]; vh[dt2*2][1]=t[1]; vh[dt2*2+1][0]=t[2]; vh[dt2*2+1][1]=t[3];
                ldsm4(t, bd + (AT_VL - AT_VH));
                vl[dt2*2][0]=t[0]; vl[dt2*2][1]=t[1]; vl[dt2*2+1][0]=t[2]; vl[dt2*2+1][1]=t[3];
            }
            #pragma unroll
            for (int nt = 0; nt < 8; nt++) {
                mma16816(pv[nt], eh, vh[nt]);
                mma16816(pv[nt], eh, vl[nt]);
                mma16816(pv[nt], el, vh[nt]);
            }
        }
        __syncthreads();             // all warps done reading V smem
        if (kt + 1 < SEQ / 128) {
            attn_load_V(sb, bh, kt + 1, tid);   // GV(kt+1): lands under next S+exp
            CPA_COMMIT();
        }
    }
    __syncthreads();

    // ---- rowsum reduce ----
    float* red   = (float*)(smem + AT_RED);
    float* rinvs = (float*)(smem + AT_RINV);
    #pragma unroll
    for (int i = 0; i < 2; i++) {
        rsum[i] += __shfl_xor_sync(0xFFFFFFFFu, rsum[i], 1);
        rsum[i] += __shfl_xor_sync(0xFFFFFFFFu, rsum[i], 2);
    }
    if (tid4 == 0) {
        red[(wm + 0 + gid) * 2 + (w & 1)] = rsum[0];
        red[(wm + 8 + gid) * 2 + (w & 1)] = rsum[1];
    }
    __syncthreads();
    if (tid < 64) {
        float ri = 1.0f / (red[tid * 2] + red[tid * 2 + 1]);
        rinvs[tid] = ri;
        g_rinv[(size_t)bh * SEQ + q0 + tid] = ri;
    }

    // ---- cross-warp PV add ----
    float* xch = (float*)(smem + AT_KH);
    if (w & 1) {
        #pragma unroll
        for (int nt = 0; nt < 8; nt++)
            #pragma unroll
            for (int i = 0; i < 4; i++)
                xch[(wg * 32 + lane) * 32 + nt * 4 + i] = pv[nt][i];
    }
    __syncthreads();
    if (!(w & 1)) {
        #pragma unroll
        for (int nt = 0; nt < 8; nt++)
            #pragma unroll
            for (int i = 0; i < 4; i++)
                pv[nt][i] += xch[(wg * 32 + lane) * 32 + nt * 4 + i];

        int b = bh >> 4, h = bh & 15;
        #pragma unroll
        for (int rh = 0; rh < 2; rh++) {
            int row = wm + rh * 8 + gid;
            float ri = rinvs[row];
            #pragma unroll
            for (int nt = 0; nt < 8; nt++) {
                float v0 = pv[nt][rh * 2 + 0] * ri;
                float v1 = pv[nt][rh * 2 + 1] * ri;
                int d = nt * 8 + tid4 * 2;
                __nv_bfloat16 h0, l0, h1, l1;
                split2(v0, h0, l0); split2(v1, h1, l1);
                size_t dst = ((size_t)(b * SEQ + q0 + row)) * DM + h * DH + d;
                *(uint32_t*)&g_attH[dst] = pack2(h0, h1);
                *(uint32_t*)&g_attL[dst] = pack2(l0, l1);
            }
        }
    }
}

// ---------------------------------------------------------------------------
// Normalize weights in place (streaming)
// ---------------------------------------------------------------------------
__global__ void norm_kernel(float* __restrict__ w) {
    size_t f4 = (size_t)blockIdx.x * blockDim.x + threadIdx.x;
    size_t fidx = f4 * 4;
    int rowi = (int)(fidx >> 11);
    float r = g_rinv[rowi];
    float4 v = *(float4*)&w[fidx];
    v.x *= r; v.y *= r; v.z *= r; v.w *= r;
    *(float4*)&w[fidx] = v;
}

// ---------------------------------------------------------------------------
extern "C" void kernel_launch(void* const* d_in, const int* in_sizes, int n_in,
                              void* d_out, int out_size) {
    const float* x  = (const float*)d_in[0];
    const float* wq = (const float*)d_in[1];
    const float* bq = (const float*)d_in[2];
    const float* wk = (const float*)d_in[3];
    const float* bk = (const float*)d_in[4];
    const float* wv = (const float*)d_in[5];
    const float* bv = (const float*)d_in[6];
    const float* wo = (const float*)d_in[7];
    const float* bo = (const float*)d_in[8];

    float* out     = (float*)d_out;
    float* weights = out + (size_t)M_TOT * DM;

    static cudaStream_t s2 = nullptr;
    static cudaEvent_t evFork = nullptr, evJoin = nullptr;
    if (!s2) {
        cudaStreamCreateWithFlags(&s2, cudaStreamNonBlocking);
        cudaEventCreateWithFlags(&evFork, cudaEventDisableTiming);
        cudaEventCreateWithFlags(&evJoin, cudaEventDisableTiming);
        cudaFuncSetAttribute(proj_qkv_kernel, cudaFuncAttributeMaxDynamicSharedMemorySize, QKV_SMEM);
        cudaFuncSetAttribute(proj_o_kernel,   cudaFuncAttributeMaxDynamicSharedMemorySize, PROJ_SMEM);
        cudaFuncSetAttribute(attn_tc_kernel,  cudaFuncAttributeMaxDynamicSharedMemorySize, ATTN_SMEM);
    }

    prep_kernel<<<8192, 256>>>(x, wq, wk, wv, wo);

    proj_qkv_kernel<<<dim3(3 * DM / 256, M_TOT / 128), 256, QKV_SMEM>>>(bq, bk, bv);

    attn_tc_kernel<<<dim3(SEQ / 64, BH_TOT), 256, ATTN_SMEM>>>(weights);

    // Fork: norm (DRAM-bound) concurrent with proj_o (tensor-bound)
    cudaEventRecord(evFork, 0);
    cudaStreamWaitEvent(s2, evFork, 0);

    size_t nf4 = (size_t)BH_TOT * SEQ * SEQ / 4;
    norm_kernel<<<(unsigned)(nf4 / 256), 256, 0, s2>>>(weights);

    proj_o_kernel<<<dim3(DM / 128, M_TOT / 128), 256, PROJ_SMEM>>>(bo, out);

    cudaEventRecord(evJoin, s2);
    cudaStreamWaitEvent(0, evJoin, 0);
}

// round 16
// speedup vs baseline: 1.3680x; 1.3140x over previous
#include <cuda_runtime.h>
#include <cuda_fp16.h>
#include <cstdint>

#define BATCH 2
#define SEQ   2048
#define DM    1024
#define NH    16
#define DH    64
#define M_TOT (BATCH*SEQ)   // 4096
#define BH_TOT (BATCH*NH)   // 32

// ---------------------------------------------------------------------------
// Scratch (__device__ globals; allocation-free rule)
// A-operands keep hi+lo (error-compensated); B-operands are plain fp16.
// ---------------------------------------------------------------------------
__device__ __half g_xH[M_TOT*DM], g_xL[M_TOT*DM];
__device__ __half g_WtH[3*DM*DM];                 // [n][k], q|k|v (hi only)
__device__ __half g_WoTH[DM*DM];                  // [n][k] (hi only)
__device__ __half g_QH[BH_TOT*SEQ*DH], g_QL[BH_TOT*SEQ*DH];
__device__ __half g_KH[BH_TOT*SEQ*DH];            // hi only
__device__ __half g_VtH[BH_TOT*DH*SEQ];           // [bh][d][s] hi only
__device__ __half g_attH[M_TOT*DM], g_attL[M_TOT*DM];
__device__ float g_rinv[BH_TOT*SEQ];

// ---------------------------------------------------------------------------
// Helpers
// ---------------------------------------------------------------------------
__device__ __forceinline__ uint32_t smem_u32(const void* p) {
    uint32_t a;
    asm("{ .reg .u64 t; cvta.to.shared.u64 t, %1; cvt.u32.u64 %0, t; }" : "=r"(a) : "l"(p));
    return a;
}
__device__ __forceinline__ void ldsm4(uint32_t* r, uint32_t a) {
    asm volatile("ldmatrix.sync.aligned.m8n8.x4.shared.b16 {%0,%1,%2,%3}, [%4];"
        : "=r"(r[0]), "=r"(r[1]), "=r"(r[2]), "=r"(r[3]) : "r"(a));
}
__device__ __forceinline__ void mma16816(float* d, const uint32_t* a, const uint32_t* b) {
    asm volatile("mma.sync.aligned.m16n8k16.row.col.f32.f16.f16.f32 "
        "{%0,%1,%2,%3},{%4,%5,%6,%7},{%8,%9},{%0,%1,%2,%3};"
        : "+f"(d[0]), "+f"(d[1]), "+f"(d[2]), "+f"(d[3])
        : "r"(a[0]), "r"(a[1]), "r"(a[2]), "r"(a[3]), "r"(b[0]), "r"(b[1]));
}
#define CPA16(s, g) asm volatile("cp.async.ca.shared.global [%0], [%1], 16;" :: "r"(s), "l"(g) : "memory")
#define CPA_COMMIT() asm volatile("cp.async.commit_group;" ::: "memory")
#define CPA_WAIT0()  asm volatile("cp.async.wait_group 0;" ::: "memory")
#define CPA_WAIT1()  asm volatile("cp.async.wait_group 1;" ::: "memory")

__device__ __forceinline__ void split2h(float v, __half& h, __half& l) {
    h = __float2half(v);
    l = __float2half(v - __half2float(h));
}
__device__ __forceinline__ uint32_t pack2h(__half a, __half b) {
    __half2 t; t.x = a; t.y = b;
    return *reinterpret_cast<uint32_t*>(&t);
}
__device__ __forceinline__ uint32_t pack2fh(float a, float b) {
    __half2 t = __floats2half2_rn(a, b);
    return *reinterpret_cast<uint32_t*>(&t);
}
__device__ __forceinline__ uint32_t pack2loh(float a, float b) {
    float ha = __half2float(__float2half(a));
    float hb = __half2float(__float2half(b));
    __half2 t = __floats2half2_rn(a - ha, b - hb);
    return *reinterpret_cast<uint32_t*>(&t);
}

// ---------------------------------------------------------------------------
// Prep (merged): blocks 0..4095 split x; blocks 4096..8191 transpose W (hi).
// ---------------------------------------------------------------------------
__global__ void prep_kernel(const float* __restrict__ x,
                            const float* __restrict__ wq, const float* __restrict__ wk,
                            const float* __restrict__ wv, const float* __restrict__ wo) {
    __shared__ float t[32][33];
    int bx = blockIdx.x, tid = threadIdx.x;
    if (bx < 4096) {
        size_t i4 = (size_t)bx * 256 + tid;
        float4 v = *(const float4*)&x[i4 * 4];
        __half h[4], l[4];
        split2h(v.x, h[0], l[0]); split2h(v.y, h[1], l[1]);
        split2h(v.z, h[2], l[2]); split2h(v.w, h[3], l[3]);
        *(uint2*)&g_xH[i4 * 4] = *(uint2*)h;
        *(uint2*)&g_xL[i4 * 4] = *(uint2*)l;
        return;
    }
    int idx = bx - 4096;
    int which = idx >> 10; idx &= 1023;
    const float* W = (which == 0) ? wq : (which == 1) ? wk : (which == 2) ? wv : wo;
    __half* H = (which < 3) ? g_WtH + (size_t)which * DM * DM : g_WoTH;
    int x0 = (idx & 31) * 32, y0 = (idx >> 5) * 32;
    int tx = tid & 31, ty = tid >> 5;
    #pragma unroll
    for (int r = 0; r < 4; r++)
        t[ty + r * 8][tx] = W[(size_t)(y0 + ty + r * 8) * DM + x0 + tx];
    __syncthreads();
    #pragma unroll
    for (int r = 0; r < 4; r++) {
        float v = t[tx][ty + r * 8];
        H[(size_t)(x0 + ty + r * 8) * DM + y0 + tx] = __float2half(v);
    }
}

// ---------------------------------------------------------------------------
// Projection GEMM mainloop (A hi+lo, B hi): 2-stage cp.async pipeline.
// ---------------------------------------------------------------------------
#define PS_AH 0
#define PS_AL 18432
#define PS_BH 36864
#define PS_STAGE 55296
#define PROJ_SMEM (2 * PS_STAGE)   // 110592

__device__ __forceinline__ void proj_prefetch(uint32_t sbs,
    const __half* __restrict__ Ah, const __half* __restrict__ Al,
    const __half* __restrict__ Bh,
    int m0, int n0, int k0, int tid) {
    #pragma unroll
    for (int e = 0; e < 4; e++) {
        int i = tid + e * 256;
        int row = i >> 3, cc = i & 7;
        size_t ga = (size_t)(m0 + row) * DM + k0 + cc * 8;
        size_t gb = (size_t)(n0 + row) * DM + k0 + cc * 8;
        uint32_t so = sbs + row * 144 + cc * 16;
        CPA16(so + PS_AH, Ah + ga);
        CPA16(so + PS_AL, Al + ga);
        CPA16(so + PS_BH, Bh + gb);
    }
}

__device__ __forceinline__ void gemm_ml(char* smem,
    const __half* __restrict__ Ah, const __half* __restrict__ Al,
    const __half* __restrict__ Bh,
    int m0, int n0, float (&c)[2][8][4]) {
    uint32_t sb0 = smem_u32(smem);
    int tid = threadIdx.x, lane = tid & 31, w = tid >> 5;
    int wm = (w >> 1) * 32, wn = (w & 1) * 64;

    proj_prefetch(sb0, Ah, Al, Bh, m0, n0, 0, tid);
    CPA_COMMIT();

    for (int s = 0; s < 16; s++) {
        if (s + 1 < 16) {
            proj_prefetch(sb0 + ((s + 1) & 1) * PS_STAGE, Ah, Al, Bh,
                          m0, n0, (s + 1) * 64, tid);
            CPA_COMMIT();
            CPA_WAIT1();
        } else {
            CPA_WAIT0();
        }
        __syncthreads();
        uint32_t sb = sb0 + (s & 1) * PS_STAGE;
        #pragma unroll
        for (int ks = 0; ks < 64; ks += 16) {
            uint32_t ah[2][4], al[2][4], bhf[8][2];
            #pragma unroll
            for (int mt = 0; mt < 2; mt++) {
                uint32_t ad = sb + PS_AH + (uint32_t)(wm + mt * 16 + (lane & 15)) * 144
                            + (ks + (lane >> 4) * 8) * 2;
                ldsm4(ah[mt], ad);
                ldsm4(al[mt], ad + (PS_AL - PS_AH));
            }
            #pragma unroll
            for (int nt2 = 0; nt2 < 4; nt2++) {
                uint32_t bd = sb + PS_BH
                            + (uint32_t)(wn + nt2 * 16 + ((lane >> 4) << 3) + (lane & 7)) * 144
                            + (ks + ((lane >> 3) & 1) * 8) * 2;
                uint32_t t[4];
                ldsm4(t, bd);
                bhf[nt2*2][0]=t[0]; bhf[nt2*2][1]=t[1]; bhf[nt2*2+1][0]=t[2]; bhf[nt2*2+1][1]=t[3];
            }
            #pragma unroll
            for (int mt = 0; mt < 2; mt++)
                #pragma unroll
                for (int nt = 0; nt < 8; nt++) {
                    mma16816(c[mt][nt], ah[mt], bhf[nt]);
                    mma16816(c[mt][nt], al[mt], bhf[nt]);
                }
        }
        __syncthreads();
    }
}

// ---------------------------------------------------------------------------
// QKV projection (128x128 tiles)
// ---------------------------------------------------------------------------
__global__ void __launch_bounds__(256, 1) proj_qkv_kernel(
    const float* __restrict__ bq, const float* __restrict__ bk, const float* __restrict__ bv) {
    extern __shared__ char smem[];
    int n0 = blockIdx.x * 128;
    int m0 = blockIdx.y * 128;
    float c[2][8][4] = {};
    gemm_ml(smem, g_xH, g_xL, g_WtH, m0, n0, c);

    int tid = threadIdx.x, lane = tid & 31, w = tid >> 5;
    int wm = (w >> 1) * 32, wn = (w & 1) * 64;
    int gid = lane >> 2, tid4 = lane & 3;
    int j = n0 >> 10, nb = n0 & 1023;
    const float* bias = (j == 0) ? bq : (j == 1) ? bk : bv;
    float scale = (j == 0) ? 0.125f : 1.0f;

    #pragma unroll
    for (int mt = 0; mt < 2; mt++)
        #pragma unroll
        for (int rh = 0; rh < 2; rh++) {
            int m = m0 + wm + mt * 16 + rh * 8 + gid;
            int b = m >> 11, s2 = m & (SEQ - 1);
            #pragma unroll
            for (int nt = 0; nt < 8; nt++) {
                int nl = nb + wn + nt * 8 + tid4 * 2;
                float v0 = (c[mt][nt][rh * 2 + 0] + bias[nl]) * scale;
                float v1 = (c[mt][nt][rh * 2 + 1] + bias[nl + 1]) * scale;
                int hh = nl >> 6, d = nl & 63;
                if (j == 0) {
                    size_t dst = (((size_t)(b * NH + hh)) * SEQ + s2) * DH + d;
                    __half h0, l0, h1, l1;
                    split2h(v0, h0, l0); split2h(v1, h1, l1);
                    *(uint32_t*)&g_QH[dst] = pack2h(h0, h1);
                    *(uint32_t*)&g_QL[dst] = pack2h(l0, l1);
                } else if (j == 1) {
                    size_t dst = (((size_t)(b * NH + hh)) * SEQ + s2) * DH + d;
                    *(uint32_t*)&g_KH[dst] = pack2fh(v0, v1);
                } else {
                    size_t dst = (((size_t)(b * NH + hh)) * DH + d) * SEQ + s2;
                    g_VtH[dst]       = __float2half(v0);
                    g_VtH[dst + SEQ] = __float2half(v1);
                }
            }
        }
}

// ---------------------------------------------------------------------------
// Output projection (128x128)
// ---------------------------------------------------------------------------
__global__ void __launch_bounds__(256, 1) proj_o_kernel(
    const float* __restrict__ bo, float* __restrict__ out) {
    extern __shared__ char smem[];
    int n0 = blockIdx.x * 128;
    int m0 = blockIdx.y * 128;
    float c[2][8][4] = {};
    gemm_ml(smem, g_attH, g_attL, g_WoTH, m0, n0, c);

    int tid = threadIdx.x, lane = tid & 31, w = tid >> 5;
    int wm = (w >> 1) * 32, wn = (w & 1) * 64;
    int gid = lane >> 2, tid4 = lane & 3;

    #pragma unroll
    for (int mt = 0; mt < 2; mt++)
        #pragma unroll
        for (int rh = 0; rh < 2; rh++) {
            int m = m0 + wm + mt * 16 + rh * 8 + gid;
            #pragma unroll
            for (int nt = 0; nt < 8; nt++) {
                int n = n0 + wn + nt * 8 + tid4 * 2;
                float2 o;
                o.x = c[mt][nt][rh * 2 + 0] + bo[n];
                o.y = c[mt][nt][rh * 2 + 1] + bo[n + 1];
                *(float2*)&out[(size_t)m * DM + n] = o;
            }
        }
}

// ---------------------------------------------------------------------------
// Attention (R12 schedule, fp16 2-term): 256 thr, q-tile 64, warp m16 x n64,
// register-E, occ 2, staggered cp.async K/V prefetch. B operands hi-only.
// ---------------------------------------------------------------------------
#define AT_QH 0
#define AT_QL 9216
#define AT_KH 18432
#define AT_VH 36864
#define AT_RED 54272
#define AT_RINV 54784
#define ATTN_SMEM 55040

__device__ __forceinline__ void attn_load_K(uint32_t sb, int bh, int kt, int tid) {
    #pragma unroll
    for (int e = 0; e < 4; e++) {
        int i = tid + e * 256;
        int row = i >> 3, c = i & 7;
        size_t g = ((size_t)bh * SEQ + kt * 128 + row) * DH + c * 8;
        CPA16(sb + AT_KH + row * 144 + c * 16, g_KH + g);
    }
}
__device__ __forceinline__ void attn_load_V(uint32_t sb, int bh, int kt, int tid) {
    #pragma unroll
    for (int e = 0; e < 4; e++) {
        int i = tid + e * 256;
        int row = i >> 4, c = i & 15;
        size_t g = ((size_t)bh * DH + row) * SEQ + kt * 128 + c * 8;
        CPA16(sb + AT_VH + row * 272 + c * 16, g_VtH + g);
    }
}

__global__ void __launch_bounds__(256, 2) attn_tc_kernel(float* __restrict__ weights) {
    extern __shared__ char smem[];
    uint32_t sb = smem_u32(smem);
    int tid = threadIdx.x, lane = tid & 31, w = tid >> 5;
    int wg = w >> 1;
    int wm = wg * 16;
    int wn = (w & 1) * 64;
    int gid = lane >> 2, tid4 = lane & 3;
    int bh = blockIdx.y, q0 = blockIdx.x * 64;

    // preamble: Q + K(0) as group A, V(0) as group B
    #pragma unroll
    for (int e = 0; e < 2; e++) {
        int i = tid + e * 256;
        int row = i >> 3, c = i & 7;
        size_t g = ((size_t)bh * SEQ + q0 + row) * DH + c * 8;
        uint32_t so = sb + AT_QH + row * 144 + c * 16;
        CPA16(so, g_QH + g);
        CPA16(so + (AT_QL - AT_QH), g_QL + g);
    }
    attn_load_K(sb, bh, 0, tid);
    CPA_COMMIT();
    attn_load_V(sb, bh, 0, tid);
    CPA_COMMIT();

    float* wbase = weights + (size_t)bh * SEQ * SEQ;
    float pv[8][4] = {};
    float rsum[2] = {};

    for (int kt = 0; kt < SEQ / 128; kt++) {
        CPA_WAIT1();                 // Q + K(kt) arrived (V(kt) may pend)
        __syncthreads();

        // ---- S = Q K^T (scale pre-folded into Q) ----
        float s[8][4] = {};
        #pragma unroll
        for (int ks = 0; ks < 64; ks += 16) {
            uint32_t ah[4], al[4], bhf[8][2];
            uint32_t ad = sb + AT_QH + (uint32_t)(wm + (lane & 15)) * 144
                        + (ks + (lane >> 4) * 8) * 2;
            ldsm4(ah, ad);
            ldsm4(al, ad + (AT_QL - AT_QH));
            #pragma unroll
            for (int nt2 = 0; nt2 < 4; nt2++) {
                uint32_t bd = sb + AT_KH
                            + (uint32_t)(wn + nt2 * 16 + ((lane >> 4) << 3) + (lane & 7)) * 144
                            + (ks + ((lane >> 3) & 1) * 8) * 2;
                uint32_t t[4];
                ldsm4(t, bd);
                bhf[nt2*2][0]=t[0]; bhf[nt2*2][1]=t[1]; bhf[nt2*2+1][0]=t[2]; bhf[nt2*2+1][1]=t[3];
            }
            #pragma unroll
            for (int nt = 0; nt < 8; nt++) {
                mma16816(s[nt], ah, bhf[nt]);
                mma16816(s[nt], al, bhf[nt]);
            }
        }
        __syncthreads();             // all warps done reading K smem
        if (kt + 1 < SEQ / 128) {
            attn_load_K(sb, bh, kt + 1, tid);   // GK(kt+1): lands under exp+PV
            CPA_COMMIT();
        }

        // ---- exp, rowsum, unnormalized weights store ----
        int row0 = q0 + wm + gid;
        #pragma unroll
        for (int nt = 0; nt < 8; nt++) {
            s[nt][0] = __expf(s[nt][0]);
            s[nt][1] = __expf(s[nt][1]);
            s[nt][2] = __expf(s[nt][2]);
            s[nt][3] = __expf(s[nt][3]);
            rsum[0] += s[nt][0] + s[nt][1];
            rsum[1] += s[nt][2] + s[nt][3];
            int col = kt * 128 + wn + nt * 8 + tid4 * 2;
            *(float2*)&wbase[(size_t)row0 * SEQ + col]       = make_float2(s[nt][0], s[nt][1]);
            *(float2*)&wbase[(size_t)(row0 + 8) * SEQ + col] = make_float2(s[nt][2], s[nt][3]);
        }

        if (kt + 1 < SEQ / 128) { CPA_WAIT1(); } else { CPA_WAIT0(); }  // V(kt) arrived
        __syncthreads();

        // ---- pv += E(this warp's k-slice) x V ----
        #pragma unroll
        for (int j = 0; j < 4; j++) {
            uint32_t eh[4], el[4];
            eh[0] = pack2fh (s[2*j][0],   s[2*j][1]);
            eh[1] = pack2fh (s[2*j][2],   s[2*j][3]);
            eh[2] = pack2fh (s[2*j+1][0], s[2*j+1][1]);
            eh[3] = pack2fh (s[2*j+1][2], s[2*j+1][3]);
            el[0] = pack2loh(s[2*j][0],   s[2*j][1]);
            el[1] = pack2loh(s[2*j][2],   s[2*j][3]);
            el[2] = pack2loh(s[2*j+1][0], s[2*j+1][1]);
            el[3] = pack2loh(s[2*j+1][2], s[2*j+1][3]);

            uint32_t vh[8][2];
            #pragma unroll
            for (int dt2 = 0; dt2 < 4; dt2++) {
                uint32_t bd = sb + AT_VH
                            + (uint32_t)(dt2 * 16 + ((lane >> 4) << 3) + (lane & 7)) * 272
                            + (wn + j * 16 + ((lane >> 3) & 1) * 8) * 2;
                uint32_t t[4];
                ldsm4(t, bd);
                vh[dt2*2][0]=t[0]; vh[dt2*2][1]=t[1]; vh[dt2*2+1][0]=t[2]; vh[dt2*2+1][1]=t[3];
            }
            #pragma unroll
            for (int nt = 0; nt < 8; nt++) {
                mma16816(pv[nt], eh, vh[nt]);
                mma16816(pv[nt], el, vh[nt]);
            }
        }
        __syncthreads();             // all warps done reading V smem
        if (kt + 1 < SEQ / 128) {
            attn_load_V(sb, bh, kt + 1, tid);   // GV(kt+1): lands under next S+exp
            CPA_COMMIT();
        }
    }
    __syncthreads();

    // ---- rowsum reduce ----
    float* red   = (float*)(smem + AT_RED);
    float* rinvs = (float*)(smem + AT_RINV);
    #pragma unroll
    for (int i = 0; i < 2; i++) {
        rsum[i] += __shfl_xor_sync(0xFFFFFFFFu, rsum[i], 1);
        rsum[i] += __shfl_xor_sync(0xFFFFFFFFu, rsum[i], 2);
    }
    if (tid4 == 0) {
        red[(wm + 0 + gid) * 2 + (w & 1)] = rsum[0];
        red[(wm + 8 + gid) * 2 + (w & 1)] = rsum[1];
    }
    __syncthreads();
    if (tid < 64) {
        float ri = 1.0f / (red[tid * 2] + red[tid * 2 + 1]);
        rinvs[tid] = ri;
        g_rinv[(size_t)bh * SEQ + q0 + tid] = ri;
    }

    // ---- cross-warp PV add (xch over K smem region, 16KB <= 18KB) ----
    float* xch = (float*)(smem + AT_KH);
    if (w & 1) {
        #pragma unroll
        for (int nt = 0; nt < 8; nt++)
            #pragma unroll
            for (int i = 0; i < 4; i++)
                xch[(wg * 32 + lane) * 32 + nt * 4 + i] = pv[nt][i];
    }
    __syncthreads();
    if (!(w & 1)) {
        #pragma unroll
        for (int nt = 0; nt < 8; nt++)
            #pragma unroll
            for (int i = 0; i < 4; i++)
                pv[nt][i] += xch[(wg * 32 + lane) * 32 + nt * 4 + i];

        int b = bh >> 4, h = bh & 15;
        #pragma unroll
        for (int rh = 0; rh < 2; rh++) {
            int row = wm + rh * 8 + gid;
            float ri = rinvs[row];
            #pragma unroll
            for (int nt = 0; nt < 8; nt++) {
                float v0 = pv[nt][rh * 2 + 0] * ri;
                float v1 = pv[nt][rh * 2 + 1] * ri;
                int d = nt * 8 + tid4 * 2;
                size_t dst = ((size_t)(b * SEQ + q0 + row)) * DM + h * DH + d;
                *(uint32_t*)&g_attH[dst] = pack2fh(v0, v1);
                *(uint32_t*)&g_attL[dst] = pack2loh(v0, v1);
            }
        }
    }
}

// ---------------------------------------------------------------------------
// Normalize weights in place (streaming)
// ---------------------------------------------------------------------------
__global__ void norm_kernel(float* __restrict__ w) {
    size_t f4 = (size_t)blockIdx.x * blockDim.x + threadIdx.x;
    size_t fidx = f4 * 4;
    int rowi = (int)(fidx >> 11);
    float r = g_rinv[rowi];
    float4 v = *(float4*)&w[fidx];
    v.x *= r; v.y *= r; v.z *= r; v.w *= r;
    *(float4*)&w[fidx] = v;
}

// ---------------------------------------------------------------------------
extern "C" void kernel_launch(void* const* d_in, const int* in_sizes, int n_in,
                              void* d_out, int out_size) {
    const float* x  = (const float*)d_in[0];
    const float* wq = (const float*)d_in[1];
    const float* bq = (const float*)d_in[2];
    const float* wk = (const float*)d_in[3];
    const float* bk = (const float*)d_in[4];
    const float* wv = (const float*)d_in[5];
    const float* bv = (const float*)d_in[6];
    const float* wo = (const float*)d_in[7];
    const float* bo = (const float*)d_in[8];

    float* out     = (float*)d_out;
    float* weights = out + (size_t)M_TOT * DM;

    static cudaStream_t s2 = nullptr;
    static cudaEvent_t evFork = nullptr, evJoin = nullptr;
    if (!s2) {
        cudaStreamCreateWithFlags(&s2, cudaStreamNonBlocking);
        cudaEventCreateWithFlags(&evFork, cudaEventDisableTiming);
        cudaEventCreateWithFlags(&evJoin, cudaEventDisableTiming);
        cudaFuncSetAttribute(proj_qkv_kernel, cudaFuncAttributeMaxDynamicSharedMemorySize, PROJ_SMEM);
        cudaFuncSetAttribute(proj_o_kernel,   cudaFuncAttributeMaxDynamicSharedMemorySize, PROJ_SMEM);
        cudaFuncSetAttribute(attn_tc_kernel,  cudaFuncAttributeMaxDynamicSharedMemorySize, ATTN_SMEM);
    }

    prep_kernel<<<8192, 256>>>(x, wq, wk, wv, wo);

    proj_qkv_kernel<<<dim3(3 * DM / 128, M_TOT / 128), 256, PROJ_SMEM>>>(bq, bk, bv);

    attn_tc_kernel<<<dim3(SEQ / 64, BH_TOT), 256, ATTN_SMEM>>>(weights);

    // Fork: norm (DRAM-bound) concurrent with proj_o (tensor-bound)
    cudaEventRecord(evFork, 0);
    cudaStreamWaitEvent(s2, evFork, 0);

    size_t nf4 = (size_t)BH_TOT * SEQ * SEQ / 4;
    norm_kernel<<<(unsigned)(nf4 / 256), 256, 0, s2>>>(weights);

    proj_o_kernel<<<dim3(DM / 128, M_TOT / 128), 256, PROJ_SMEM>>>(bo, out);

    cudaEventRecord(evJoin, s2);
    cudaStreamWaitEvent(0, evJoin, 0);
}

// round 17
// speedup vs baseline: 1.4586x; 1.0662x over previous
#include <cuda_runtime.h>
#include <cuda_fp16.h>
#include <cstdint>

#define BATCH 2
#define SEQ   2048
#define DM    1024
#define NH    16
#define DH    64
#define M_TOT (BATCH*SEQ)   // 4096
#define BH_TOT (BATCH*NH)   // 32

// ---------------------------------------------------------------------------
// Scratch (__device__ globals; allocation-free rule)
// x and attended keep hi+lo (feed the 2-term projections); Q/K/V/W are fp16.
// ---------------------------------------------------------------------------
__device__ __half g_xH[M_TOT*DM], g_xL[M_TOT*DM];
__device__ __half g_WtH[3*DM*DM];                 // [n][k], q|k|v
__device__ __half g_WoTH[DM*DM];                  // [n][k]
__device__ __half g_QH[BH_TOT*SEQ*DH];            // fp16 (scale folded)
__device__ __half g_KH[BH_TOT*SEQ*DH];
__device__ __half g_VtH[BH_TOT*DH*SEQ];           // [bh][d][s]
__device__ __half g_attH[M_TOT*DM], g_attL[M_TOT*DM];
__device__ float g_rinv[BH_TOT*SEQ];

// ---------------------------------------------------------------------------
// Helpers
// ---------------------------------------------------------------------------
__device__ __forceinline__ uint32_t smem_u32(const void* p) {
    uint32_t a;
    asm("{ .reg .u64 t; cvta.to.shared.u64 t, %1; cvt.u32.u64 %0, t; }" : "=r"(a) : "l"(p));
    return a;
}
__device__ __forceinline__ void ldsm4(uint32_t* r, uint32_t a) {
    asm volatile("ldmatrix.sync.aligned.m8n8.x4.shared.b16 {%0,%1,%2,%3}, [%4];"
        : "=r"(r[0]), "=r"(r[1]), "=r"(r[2]), "=r"(r[3]) : "r"(a));
}
__device__ __forceinline__ void mma16816(float* d, const uint32_t* a, const uint32_t* b) {
    asm volatile("mma.sync.aligned.m16n8k16.row.col.f32.f16.f16.f32 "
        "{%0,%1,%2,%3},{%4,%5,%6,%7},{%8,%9},{%0,%1,%2,%3};"
        : "+f"(d[0]), "+f"(d[1]), "+f"(d[2]), "+f"(d[3])
        : "r"(a[0]), "r"(a[1]), "r"(a[2]), "r"(a[3]), "r"(b[0]), "r"(b[1]));
}
#define CPA16(s, g) asm volatile("cp.async.ca.shared.global [%0], [%1], 16;" :: "r"(s), "l"(g) : "memory")
#define CPA_COMMIT() asm volatile("cp.async.commit_group;" ::: "memory")
#define CPA_WAIT0()  asm volatile("cp.async.wait_group 0;" ::: "memory")
#define CPA_WAIT1()  asm volatile("cp.async.wait_group 1;" ::: "memory")

__device__ __forceinline__ void split2h(float v, __half& h, __half& l) {
    h = __float2half(v);
    l = __float2half(v - __half2float(h));
}
__device__ __forceinline__ uint32_t pack2h(__half a, __half b) {
    __half2 t; t.x = a; t.y = b;
    return *reinterpret_cast<uint32_t*>(&t);
}
__device__ __forceinline__ uint32_t pack2fh(float a, float b) {
    __half2 t = __floats2half2_rn(a, b);
    return *reinterpret_cast<uint32_t*>(&t);
}
__device__ __forceinline__ uint32_t pack2loh(float a, float b) {
    float ha = __half2float(__float2half(a));
    float hb = __half2float(__float2half(b));
    __half2 t = __floats2half2_rn(a - ha, b - hb);
    return *reinterpret_cast<uint32_t*>(&t);
}

// ---------------------------------------------------------------------------
// Prep (merged): blocks 0..4095 split x; blocks 4096..8191 transpose W (hi).
// ---------------------------------------------------------------------------
__global__ void prep_kernel(const float* __restrict__ x,
                            const float* __restrict__ wq, const float* __restrict__ wk,
                            const float* __restrict__ wv, const float* __restrict__ wo) {
    __shared__ float t[32][33];
    int bx = blockIdx.x, tid = threadIdx.x;
    if (bx < 4096) {
        size_t i4 = (size_t)bx * 256 + tid;
        float4 v = *(const float4*)&x[i4 * 4];
        __half h[4], l[4];
        split2h(v.x, h[0], l[0]); split2h(v.y, h[1], l[1]);
        split2h(v.z, h[2], l[2]); split2h(v.w, h[3], l[3]);
        *(uint2*)&g_xH[i4 * 4] = *(uint2*)h;
        *(uint2*)&g_xL[i4 * 4] = *(uint2*)l;
        return;
    }
    int idx = bx - 4096;
    int which = idx >> 10; idx &= 1023;
    const float* W = (which == 0) ? wq : (which == 1) ? wk : (which == 2) ? wv : wo;
    __half* H = (which < 3) ? g_WtH + (size_t)which * DM * DM : g_WoTH;
    int x0 = (idx & 31) * 32, y0 = (idx >> 5) * 32;
    int tx = tid & 31, ty = tid >> 5;
    #pragma unroll
    for (int r = 0; r < 4; r++)
        t[ty + r * 8][tx] = W[(size_t)(y0 + ty + r * 8) * DM + x0 + tx];
    __syncthreads();
    #pragma unroll
    for (int r = 0; r < 4; r++) {
        float v = t[tx][ty + r * 8];
        H[(size_t)(x0 + ty + r * 8) * DM + y0 + tx] = __float2half(v);
    }
}

// ---------------------------------------------------------------------------
// Projection GEMM mainloop (A hi+lo, B hi): 2-stage cp.async pipeline.
// ---------------------------------------------------------------------------
#define PS_AH 0
#define PS_AL 18432
#define PS_BH 36864
#define PS_STAGE 55296
#define PROJ_SMEM (2 * PS_STAGE)   // 110592

__device__ __forceinline__ void proj_prefetch(uint32_t sbs,
    const __half* __restrict__ Ah, const __half* __restrict__ Al,
    const __half* __restrict__ Bh,
    int m0, int n0, int k0, int tid) {
    #pragma unroll
    for (int e = 0; e < 4; e++) {
        int i = tid + e * 256;
        int row = i >> 3, cc = i & 7;
        size_t ga = (size_t)(m0 + row) * DM + k0 + cc * 8;
        size_t gb = (size_t)(n0 + row) * DM + k0 + cc * 8;
        uint32_t so = sbs + row * 144 + cc * 16;
        CPA16(so + PS_AH, Ah + ga);
        CPA16(so + PS_AL, Al + ga);
        CPA16(so + PS_BH, Bh + gb);
    }
}

__device__ __forceinline__ void gemm_ml(char* smem,
    const __half* __restrict__ Ah, const __half* __restrict__ Al,
    const __half* __restrict__ Bh,
    int m0, int n0, float (&c)[2][8][4]) {
    uint32_t sb0 = smem_u32(smem);
    int tid = threadIdx.x, lane = tid & 31, w = tid >> 5;
    int wm = (w >> 1) * 32, wn = (w & 1) * 64;

    proj_prefetch(sb0, Ah, Al, Bh, m0, n0, 0, tid);
    CPA_COMMIT();

    for (int s = 0; s < 16; s++) {
        if (s + 1 < 16) {
            proj_prefetch(sb0 + ((s + 1) & 1) * PS_STAGE, Ah, Al, Bh,
                          m0, n0, (s + 1) * 64, tid);
            CPA_COMMIT();
            CPA_WAIT1();
        } else {
            CPA_WAIT0();
        }
        __syncthreads();
        uint32_t sb = sb0 + (s & 1) * PS_STAGE;
        #pragma unroll
        for (int ks = 0; ks < 64; ks += 16) {
            uint32_t ah[2][4], al[2][4], bhf[8][2];
            #pragma unroll
            for (int mt = 0; mt < 2; mt++) {
                uint32_t ad = sb + PS_AH + (uint32_t)(wm + mt * 16 + (lane & 15)) * 144
                            + (ks + (lane >> 4) * 8) * 2;
                ldsm4(ah[mt], ad);
                ldsm4(al[mt], ad + (PS_AL - PS_AH));
            }
            #pragma unroll
            for (int nt2 = 0; nt2 < 4; nt2++) {
                uint32_t bd = sb + PS_BH
                            + (uint32_t)(wn + nt2 * 16 + ((lane >> 4) << 3) + (lane & 7)) * 144
                            + (ks + ((lane >> 3) & 1) * 8) * 2;
                uint32_t t[4];
                ldsm4(t, bd);
                bhf[nt2*2][0]=t[0]; bhf[nt2*2][1]=t[1]; bhf[nt2*2+1][0]=t[2]; bhf[nt2*2+1][1]=t[3];
            }
            #pragma unroll
            for (int mt = 0; mt < 2; mt++)
                #pragma unroll
                for (int nt = 0; nt < 8; nt++) {
                    mma16816(c[mt][nt], ah[mt], bhf[nt]);
                    mma16816(c[mt][nt], al[mt], bhf[nt]);
                }
        }
        __syncthreads();
    }
}

// ---------------------------------------------------------------------------
// QKV projection (128x128 tiles)
// ---------------------------------------------------------------------------
__global__ void __launch_bounds__(256, 1) proj_qkv_kernel(
    const float* __restrict__ bq, const float* __restrict__ bk, const float* __restrict__ bv) {
    extern __shared__ char smem[];
    int n0 = blockIdx.x * 128;
    int m0 = blockIdx.y * 128;
    float c[2][8][4] = {};
    gemm_ml(smem, g_xH, g_xL, g_WtH, m0, n0, c);

    int tid = threadIdx.x, lane = tid & 31, w = tid >> 5;
    int wm = (w >> 1) * 32, wn = (w & 1) * 64;
    int gid = lane >> 2, tid4 = lane & 3;
    int j = n0 >> 10, nb = n0 & 1023;
    const float* bias = (j == 0) ? bq : (j == 1) ? bk : bv;
    float scale = (j == 0) ? 0.125f : 1.0f;
    __half* dQ = (j == 0) ? g_QH : g_KH;

    #pragma unroll
    for (int mt = 0; mt < 2; mt++)
        #pragma unroll
        for (int rh = 0; rh < 2; rh++) {
            int m = m0 + wm + mt * 16 + rh * 8 + gid;
            int b = m >> 11, s2 = m & (SEQ - 1);
            #pragma unroll
            for (int nt = 0; nt < 8; nt++) {
                int nl = nb + wn + nt * 8 + tid4 * 2;
                float v0 = (c[mt][nt][rh * 2 + 0] + bias[nl]) * scale;
                float v1 = (c[mt][nt][rh * 2 + 1] + bias[nl + 1]) * scale;
                int hh = nl >> 6, d = nl & 63;
                if (j < 2) {
                    size_t dst = (((size_t)(b * NH + hh)) * SEQ + s2) * DH + d;
                    *(uint32_t*)&dQ[dst] = pack2fh(v0, v1);
                } else {
                    size_t dst = (((size_t)(b * NH + hh)) * DH + d) * SEQ + s2;
                    g_VtH[dst]       = __float2half(v0);
                    g_VtH[dst + SEQ] = __float2half(v1);
                }
            }
        }
}

// ---------------------------------------------------------------------------
// Output projection (128x128)
// ---------------------------------------------------------------------------
__global__ void __launch_bounds__(256, 1) proj_o_kernel(
    const float* __restrict__ bo, float* __restrict__ out) {
    extern __shared__ char smem[];
    int n0 = blockIdx.x * 128;
    int m0 = blockIdx.y * 128;
    float c[2][8][4] = {};
    gemm_ml(smem, g_attH, g_attL, g_WoTH, m0, n0, c);

    int tid = threadIdx.x, lane = tid & 31, w = tid >> 5;
    int wm = (w >> 1) * 32, wn = (w & 1) * 64;
    int gid = lane >> 2, tid4 = lane & 3;

    #pragma unroll
    for (int mt = 0; mt < 2; mt++)
        #pragma unroll
        for (int rh = 0; rh < 2; rh++) {
            int m = m0 + wm + mt * 16 + rh * 8 + gid;
            #pragma unroll
            for (int nt = 0; nt < 8; nt++) {
                int n = n0 + wn + nt * 8 + tid4 * 2;
                float2 o;
                o.x = c[mt][nt][rh * 2 + 0] + bo[n];
                o.y = c[mt][nt][rh * 2 + 1] + bo[n + 1];
                *(float2*)&out[(size_t)m * DM + n] = o;
            }
        }
}

// ---------------------------------------------------------------------------
// Attention (fp16 1-term Q and E; K/V fp16): R12 schedule, 256 thr,
// q-tile 64, warp m16 x n64, register-E, occ 2, staggered cp.async prefetch.
// ---------------------------------------------------------------------------
#define AT_QH 0
#define AT_KH 9216
#define AT_VH 27648
#define AT_RED 45056
#define AT_RINV 45568
#define ATTN_SMEM 46080

__device__ __forceinline__ void attn_load_K(uint32_t sb, int bh, int kt, int tid) {
    #pragma unroll
    for (int e = 0; e < 4; e++) {
        int i = tid + e * 256;
        int row = i >> 3, c = i & 7;
        size_t g = ((size_t)bh * SEQ + kt * 128 + row) * DH + c * 8;
        CPA16(sb + AT_KH + row * 144 + c * 16, g_KH + g);
    }
}
__device__ __forceinline__ void attn_load_V(uint32_t sb, int bh, int kt, int tid) {
    #pragma unroll
    for (int e = 0; e < 4; e++) {
        int i = tid + e * 256;
        int row = i >> 4, c = i & 15;
        size_t g = ((size_t)bh * DH + row) * SEQ + kt * 128 + c * 8;
        CPA16(sb + AT_VH + row * 272 + c * 16, g_VtH + g);
    }
}

__global__ void __launch_bounds__(256, 2) attn_tc_kernel(float* __restrict__ weights) {
    extern __shared__ char smem[];
    uint32_t sb = smem_u32(smem);
    int tid = threadIdx.x, lane = tid & 31, w = tid >> 5;
    int wg = w >> 1;
    int wm = wg * 16;
    int wn = (w & 1) * 64;
    int gid = lane >> 2, tid4 = lane & 3;
    int bh = blockIdx.y, q0 = blockIdx.x * 64;

    // preamble: Q + K(0) as group A, V(0) as group B
    #pragma unroll
    for (int e = 0; e < 2; e++) {
        int i = tid + e * 256;
        int row = i >> 3, c = i & 7;
        size_t g = ((size_t)bh * SEQ + q0 + row) * DH + c * 8;
        CPA16(sb + AT_QH + row * 144 + c * 16, g_QH + g);
    }
    attn_load_K(sb, bh, 0, tid);
    CPA_COMMIT();
    attn_load_V(sb, bh, 0, tid);
    CPA_COMMIT();

    float* wbase = weights + (size_t)bh * SEQ * SEQ;
    float pv[8][4] = {};
    float rsum[2] = {};

    for (int kt = 0; kt < SEQ / 128; kt++) {
        CPA_WAIT1();                 // Q + K(kt) arrived (V(kt) may pend)
        __syncthreads();

        // ---- S = Q K^T (scale pre-folded into Q) ----
        float s[8][4] = {};
        #pragma unroll
        for (int ks = 0; ks < 64; ks += 16) {
            uint32_t ah[4], bhf[8][2];
            uint32_t ad = sb + AT_QH + (uint32_t)(wm + (lane & 15)) * 144
                        + (ks + (lane >> 4) * 8) * 2;
            ldsm4(ah, ad);
            #pragma unroll
            for (int nt2 = 0; nt2 < 4; nt2++) {
                uint32_t bd = sb + AT_KH
                            + (uint32_t)(wn + nt2 * 16 + ((lane >> 4) << 3) + (lane & 7)) * 144
                            + (ks + ((lane >> 3) & 1) * 8) * 2;
                uint32_t t[4];
                ldsm4(t, bd);
                bhf[nt2*2][0]=t[0]; bhf[nt2*2][1]=t[1]; bhf[nt2*2+1][0]=t[2]; bhf[nt2*2+1][1]=t[3];
            }
            #pragma unroll
            for (int nt = 0; nt < 8; nt++)
                mma16816(s[nt], ah, bhf[nt]);
        }
        __syncthreads();             // all warps done reading K smem
        if (kt + 1 < SEQ / 128) {
            attn_load_K(sb, bh, kt + 1, tid);   // GK(kt+1): lands under exp+PV
            CPA_COMMIT();
        }

        // ---- exp, rowsum, unnormalized weights store ----
        int row0 = q0 + wm + gid;
        #pragma unroll
        for (int nt = 0; nt < 8; nt++) {
            s[nt][0] = __expf(s[nt][0]);
            s[nt][1] = __expf(s[nt][1]);
            s[nt][2] = __expf(s[nt][2]);
            s[nt][3] = __expf(s[nt][3]);
            rsum[0] += s[nt][0] + s[nt][1];
            rsum[1] += s[nt][2] + s[nt][3];
            int col = kt * 128 + wn + nt * 8 + tid4 * 2;
            *(float2*)&wbase[(size_t)row0 * SEQ + col]       = make_float2(s[nt][0], s[nt][1]);
            *(float2*)&wbase[(size_t)(row0 + 8) * SEQ + col] = make_float2(s[nt][2], s[nt][3]);
        }

        if (kt + 1 < SEQ / 128) { CPA_WAIT1(); } else { CPA_WAIT0(); }  // V(kt) arrived
        __syncthreads();

        // ---- pv += E(this warp's k-slice) x V ----
        #pragma unroll
        for (int j = 0; j < 4; j++) {
            uint32_t eh[4];
            eh[0] = pack2fh(s[2*j][0],   s[2*j][1]);
            eh[1] = pack2fh(s[2*j][2],   s[2*j][3]);
            eh[2] = pack2fh(s[2*j+1][0], s[2*j+1][1]);
            eh[3] = pack2fh(s[2*j+1][2], s[2*j+1][3]);

            uint32_t vh[8][2];
            #pragma unroll
            for (int dt2 = 0; dt2 < 4; dt2++) {
                uint32_t bd = sb + AT_VH
                            + (uint32_t)(dt2 * 16 + ((lane >> 4) << 3) + (lane & 7)) * 272
                            + (wn + j * 16 + ((lane >> 3) & 1) * 8) * 2;
                uint32_t t[4];
                ldsm4(t, bd);
                vh[dt2*2][0]=t[0]; vh[dt2*2][1]=t[1]; vh[dt2*2+1][0]=t[2]; vh[dt2*2+1][1]=t[3];
            }
            #pragma unroll
            for (int nt = 0; nt < 8; nt++)
                mma16816(pv[nt], eh, vh[nt]);
        }
        __syncthreads();             // all warps done reading V smem
        if (kt + 1 < SEQ / 128) {
            attn_load_V(sb, bh, kt + 1, tid);   // GV(kt+1): lands under next S+exp
            CPA_COMMIT();
        }
    }
    __syncthreads();

    // ---- rowsum reduce ----
    float* red   = (float*)(smem + AT_RED);
    float* rinvs = (float*)(smem + AT_RINV);
    #pragma unroll
    for (int i = 0; i < 2; i++) {
        rsum[i] += __shfl_xor_sync(0xFFFFFFFFu, rsum[i], 1);
        rsum[i] += __shfl_xor_sync(0xFFFFFFFFu, rsum[i], 2);
    }
    if (tid4 == 0) {
        red[(wm + 0 + gid) * 2 + (w & 1)] = rsum[0];
        red[(wm + 8 + gid) * 2 + (w & 1)] = rsum[1];
    }
    __syncthreads();
    if (tid < 64) {
        float ri = 1.0f / (red[tid * 2] + red[tid * 2 + 1]);
        rinvs[tid] = ri;
        g_rinv[(size_t)bh * SEQ + q0 + tid] = ri;
    }

    // ---- cross-warp PV add (xch over K smem region, 16KB <= 18KB) ----
    float* xch = (float*)(smem + AT_KH);
    if (w & 1) {
        #pragma unroll
        for (int nt = 0; nt < 8; nt++)
            #pragma unroll
            for (int i = 0; i < 4; i++)
                xch[(wg * 32 + lane) * 32 + nt * 4 + i] = pv[nt][i];
    }
    __syncthreads();
    if (!(w & 1)) {
        #pragma unroll
        for (int nt = 0; nt < 8; nt++)
            #pragma unroll
            for (int i = 0; i < 4; i++)
                pv[nt][i] += xch[(wg * 32 + lane) * 32 + nt * 4 + i];

        int b = bh >> 4, h = bh & 15;
        #pragma unroll
        for (int rh = 0; rh < 2; rh++) {
            int row = wm + rh * 8 + gid;
            float ri = rinvs[row];
            #pragma unroll
            for (int nt = 0; nt < 8; nt++) {
                float v0 = pv[nt][rh * 2 + 0] * ri;
                float v1 = pv[nt][rh * 2 + 1] * ri;
                int d = nt * 8 + tid4 * 2;
                size_t dst = ((size_t)(b * SEQ + q0 + row)) * DM + h * DH + d;
                *(uint32_t*)&g_attH[dst] = pack2fh(v0, v1);
                *(uint32_t*)&g_attL[dst] = pack2loh(v0, v1);
            }
        }
    }
}

// ---------------------------------------------------------------------------
// Normalize weights in place (streaming)
// ---------------------------------------------------------------------------
__global__ void norm_kernel(float* __restrict__ w) {
    size_t f4 = (size_t)blockIdx.x * blockDim.x + threadIdx.x;
    size_t fidx = f4 * 4;
    int rowi = (int)(fidx >> 11);
    float r = g_rinv[rowi];
    float4 v = *(float4*)&w[fidx];
    v.x *= r; v.y *= r; v.z *= r; v.w *= r;
    *(float4*)&w[fidx] = v;
}

// ---------------------------------------------------------------------------
extern "C" void kernel_launch(void* const* d_in, const int* in_sizes, int n_in,
                              void* d_out, int out_size) {
    const float* x  = (const float*)d_in[0];
    const float* wq = (const float*)d_in[1];
    const float* bq = (const float*)d_in[2];
    const float* wk = (const float*)d_in[3];
    const float* bk = (const float*)d_in[4];
    const float* wv = (const float*)d_in[5];
    const float* bv = (const float*)d_in[6];
    const float* wo = (const float*)d_in[7];
    const float* bo = (const float*)d_in[8];

    float* out     = (float*)d_out;
    float* weights = out + (size_t)M_TOT * DM;

    static cudaStream_t s2 = nullptr;
    static cudaEvent_t evFork = nullptr, evJoin = nullptr;
    if (!s2) {
        cudaStreamCreateWithFlags(&s2, cudaStreamNonBlocking);
        cudaEventCreateWithFlags(&evFork, cudaEventDisableTiming);
        cudaEventCreateWithFlags(&evJoin, cudaEventDisableTiming);
        cudaFuncSetAttribute(proj_qkv_kernel, cudaFuncAttributeMaxDynamicSharedMemorySize, PROJ_SMEM);
        cudaFuncSetAttribute(proj_o_kernel,   cudaFuncAttributeMaxDynamicSharedMemorySize, PROJ_SMEM);
        cudaFuncSetAttribute(attn_tc_kernel,  cudaFuncAttributeMaxDynamicSharedMemorySize, ATTN_SMEM);
    }

    prep_kernel<<<8192, 256>>>(x, wq, wk, wv, wo);

    proj_qkv_kernel<<<dim3(3 * DM / 128, M_TOT / 128), 256, PROJ_SMEM>>>(bq, bk, bv);

    attn_tc_kernel<<<dim3(SEQ / 64, BH_TOT), 256, ATTN_SMEM>>>(weights);

    // Fork: norm (DRAM-bound) concurrent with proj_o (tensor-bound)
    cudaEventRecord(evFork, 0);
    cudaStreamWaitEvent(s2, evFork, 0);

    size_t nf4 = (size_t)BH_TOT * SEQ * SEQ / 4;
    norm_kernel<<<(unsigned)(nf4 / 256), 256, 0, s2>>>(weights);

    proj_o_kernel<<<dim3(DM / 128, M_TOT / 128), 256, PROJ_SMEM>>>(bo, out);

    cudaEventRecord(evJoin, s2);
    cudaStreamWaitEvent(0, evJoin, 0);
}